// round 6
// baseline (speedup 1.0000x reference)
#include <cuda_runtime.h>
#include <cuda_bf16.h>
#include <cstddef>

// Problem constants
#define S_DIM 64
#define B_DIM 4
#define N_DIM 256
#define D_MODEL 256
#define HEADS 8
#define DHEAD 32
#define INNER 256            // HEADS * DIM_HEAD
#define QKV_COLS 768         // 3 * INNER
#define M_TOTAL (S_DIM * B_DIM * N_DIM)   // 65536
#define SCALE 0.17677669529663687f        // 32^-0.5

typedef unsigned long long ull;

// ---- packed f32x2 helpers (sm_103a FFMA2 path, PTX-only) ----
__device__ __forceinline__ ull fma2(ull a, ull b, ull c) {
    ull d;
    asm("fma.rn.f32x2 %0, %1, %2, %3;" : "=l"(d) : "l"(a), "l"(b), "l"(c));
    return d;
}
__device__ __forceinline__ ull add2(ull a, ull b) {
    ull d;
    asm("add.rn.f32x2 %0, %1, %2;" : "=l"(d) : "l"(a), "l"(b));
    return d;
}
__device__ __forceinline__ ull pack2(float lo, float hi) {
    ull d;
    asm("mov.b64 %0, {%1, %2};" : "=l"(d) : "f"(lo), "f"(hi));
    return d;
}
__device__ __forceinline__ float2 unpack2(ull v) {
    float lo, hi;
    asm("mov.b64 {%0, %1}, %2;" : "=f"(lo), "=f"(hi) : "l"(v));
    return make_float2(lo, hi);
}

// Scratch (allocation-free rule: __device__ globals)
__device__ float g_qkv[(size_t)M_TOTAL * QKV_COLS];   // 192 MB
__device__ float g_attn[(size_t)M_TOTAL * INNER];     // 64 MB
__device__ unsigned g_maskpack[S_DIM][N_DIM][8];      // bit-packed mask per s

// ---------------------------------------------------------------------------
// Mask pre-pack: one block per s, thread i packs row i (8 words of 32 bits).
// ---------------------------------------------------------------------------
__global__ void pack_mask_kernel(const int* __restrict__ mask) {
    const int s = blockIdx.x;
    const int i = threadIdx.x;
    const int* p = mask + ((size_t)s * N_DIM + i) * N_DIM;
    #pragma unroll
    for (int c = 0; c < 8; c++) {
        unsigned bits = 0;
        #pragma unroll 8
        for (int bb = 0; bb < 32; bb++)
            bits |= (unsigned)(p[c * 32 + bb] != 0) << bb;
        g_maskpack[s][i][c] = bits;
    }
}

// ---------------------------------------------------------------------------
// SGEMM: C[M,N] = A[M,K] @ B[K,N] (+ bias). 128x128 block, 8x8 per thread.
// A stored in SMEM as pre-duplicated f32 pairs (a,a) so the inner loop is
// pure LDS + FFMA2 — no register-duplication MOVs.
// ---------------------------------------------------------------------------
#define BM 128
#define BN 128
#define BK 16
#define TM 8
#define TN 8

__global__ __launch_bounds__(256, 2)
void sgemm_kernel(const float* __restrict__ A, const float* __restrict__ B,
                  const float* __restrict__ bias, float* __restrict__ C,
                  int M, int N, int K) {
    __shared__ ull   As2[BK][BM];   // duplicated pairs: As2[k][m] = (A[m][k], A[m][k])
    __shared__ float Bs[BK][BN];

    const int tid = threadIdx.x;
    const int bx = blockIdx.x;   // N tile
    const int by = blockIdx.y;   // M tile

    const int tcol = tid % (BN / TN);   // 0..15
    const int trow = tid / (BN / TN);   // 0..15

    const int arow  = tid / 4;          // 0..63
    const int acol4 = (tid % 4) * 4;    // 0,4,8,12
    const int brow  = tid / 32;         // 0..7
    const int bcol4 = (tid % 32) * 4;

    const float* Ab = A + (size_t)by * BM * K;
    const float* Bb = B + (size_t)bx * BN;

    ull accp[TM][TN / 2];
    #pragma unroll
    for (int i = 0; i < TM; i++)
        #pragma unroll
        for (int j = 0; j < TN / 2; j++) accp[i][j] = 0ull;

    for (int kk = 0; kk < K; kk += BK) {
        #pragma unroll
        for (int r = 0; r < 2; r++) {
            int ar = arow + r * 64;
            float4 v = *(const float4*)(Ab + (size_t)ar * K + kk + acol4);
            As2[acol4 + 0][ar] = pack2(v.x, v.x);
            As2[acol4 + 1][ar] = pack2(v.y, v.y);
            As2[acol4 + 2][ar] = pack2(v.z, v.z);
            As2[acol4 + 3][ar] = pack2(v.w, v.w);
        }
        #pragma unroll
        for (int r = 0; r < 2; r++) {
            int br = brow + r * 8;
            *(float4*)&Bs[br][bcol4] =
                *(const float4*)(Bb + (size_t)(kk + br) * N + bcol4);
        }
        __syncthreads();

        #pragma unroll
        for (int k = 0; k < BK; k++) {
            // A: 8 duplicated pairs (broadcast within warp), B: 4 natural pairs
            ulonglong2 A01 = *(const ulonglong2*)&As2[k][trow * TM + 0];
            ulonglong2 A23 = *(const ulonglong2*)&As2[k][trow * TM + 2];
            ulonglong2 A45 = *(const ulonglong2*)&As2[k][trow * TM + 4];
            ulonglong2 A67 = *(const ulonglong2*)&As2[k][trow * TM + 6];
            ulonglong2 b0 = *(const ulonglong2*)&Bs[k][tcol * TN];
            ulonglong2 b1 = *(const ulonglong2*)&Bs[k][tcol * TN + 4];
            ull ra[TM] = {A01.x, A01.y, A23.x, A23.y, A45.x, A45.y, A67.x, A67.y};
            ull rb[4]  = {b0.x, b0.y, b1.x, b1.y};
            #pragma unroll
            for (int i = 0; i < TM; i++) {
                #pragma unroll
                for (int jp = 0; jp < TN / 2; jp++)
                    accp[i][jp] = fma2(ra[i], rb[jp], accp[i][jp]);
            }
        }
        __syncthreads();
    }

    // Epilogue
    #pragma unroll
    for (int i = 0; i < TM; i++) {
        size_t row = (size_t)by * BM + trow * TM + i;
        float* Cp = C + row * N + (size_t)bx * BN + tcol * TN;
        #pragma unroll
        for (int jq = 0; jq < 2; jq++) {
            float2 u0 = unpack2(accp[i][2 * jq + 0]);
            float2 u1 = unpack2(accp[i][2 * jq + 1]);
            float4 v = make_float4(u0.x, u0.y, u1.x, u1.y);
            if (bias) {
                const float* bp = bias + (size_t)bx * BN + tcol * TN + jq * 4;
                v.x += bp[0]; v.y += bp[1]; v.z += bp[2]; v.w += bp[3];
            }
            *(float4*)(Cp + jq * 4) = v;
        }
    }
}

// ---------------------------------------------------------------------------
// Attention: one block of 128 threads per (s, b, h); thread t owns query
// rows t and t+128 (K/V LDS amortized over 2 rows). No-max softmax
// (scores are O(1); masked -> p=0), packed f32x2 FMAs.
// smem = K 32KB + V 32KB = 64 KB -> 2 CTAs/SM -> 2 warps/SMSP.
// q read directly from GMEM; mask read pre-packed from GMEM.
// ---------------------------------------------------------------------------
#define ATTN_SMEM_BYTES ((256 * 32 + 256 * 32) * 4)

__global__ __launch_bounds__(128, 2)
void attn_kernel(const float* __restrict__ qkv, float* __restrict__ outp) {
    extern __shared__ float sm[];
    float* sm_k = sm;                  // [256][32]
    float* sm_v = sm_k + 256 * 32;     // [256][32]

    const int tid = threadIdx.x;
    const int h = blockIdx.x;
    const int b = blockIdx.y;
    const int s = blockIdx.z;

    const size_t base = ((size_t)(s * B_DIM + b) * N_DIM) * QKV_COLS;
    const int qoff = h * DHEAD;
    const int koff = INNER + h * DHEAD;
    const int voff = 2 * INNER + h * DHEAD;

    // cooperative load k/v tiles (float4, coalesced per-row)
    for (int idx = tid; idx < 256 * 8; idx += 128) {
        int j  = idx >> 3;
        int d4 = (idx & 7) * 4;
        const float* rowp = qkv + base + (size_t)j * QKV_COLS;
        *(float4*)&sm_k[j * 32 + d4] = *(const float4*)(rowp + koff + d4);
        *(float4*)&sm_v[j * 32 + d4] = *(const float4*)(rowp + voff + d4);
    }

    const int i0 = tid;
    const int i1 = tid + 128;

    // q rows straight from GMEM, pre-scaled, packed into f32 pairs
    ull q0p[16], q1p[16];
    {
        const float* q0 = qkv + base + (size_t)i0 * QKV_COLS + qoff;
        const float* q1 = qkv + base + (size_t)i1 * QKV_COLS + qoff;
        #pragma unroll
        for (int d4 = 0; d4 < 8; d4++) {
            float4 t0 = *(const float4*)(q0 + d4 * 4);
            float4 t1 = *(const float4*)(q1 + d4 * 4);
            q0p[2 * d4 + 0] = pack2(t0.x * SCALE, t0.y * SCALE);
            q0p[2 * d4 + 1] = pack2(t0.z * SCALE, t0.w * SCALE);
            q1p[2 * d4 + 0] = pack2(t1.x * SCALE, t1.y * SCALE);
            q1p[2 * d4 + 1] = pack2(t1.z * SCALE, t1.w * SCALE);
        }
    }
    __syncthreads();

    ull acc0[16], acc1[16];
    #pragma unroll
    for (int d = 0; d < 16; d++) { acc0[d] = 0ull; acc1[d] = 0ull; }
    float l0 = 0.0f, l1 = 0.0f;

    for (int jw = 0; jw < 8; jw++) {
        const unsigned mb0 = g_maskpack[s][i0][jw];
        const unsigned mb1 = g_maskpack[s][i1][jw];
        #pragma unroll 2
        for (int jj = 0; jj < 32; jj++) {
            const int j = jw * 32 + jj;
            const ulonglong2* kp = (const ulonglong2*)&sm_k[j * 32];
            ull a0[4] = {0ull, 0ull, 0ull, 0ull};
            ull a1[4] = {0ull, 0ull, 0ull, 0ull};
            #pragma unroll
            for (int d = 0; d < 8; d++) {
                ulonglong2 kk = kp[d];
                a0[(2 * d + 0) & 3] = fma2(q0p[2 * d + 0], kk.x, a0[(2 * d + 0) & 3]);
                a0[(2 * d + 1) & 3] = fma2(q0p[2 * d + 1], kk.y, a0[(2 * d + 1) & 3]);
                a1[(2 * d + 0) & 3] = fma2(q1p[2 * d + 0], kk.x, a1[(2 * d + 0) & 3]);
                a1[(2 * d + 1) & 3] = fma2(q1p[2 * d + 1], kk.y, a1[(2 * d + 1) & 3]);
            }
            float2 r0 = unpack2(add2(add2(a0[0], a0[1]), add2(a0[2], a0[3])));
            float2 r1 = unpack2(add2(add2(a1[0], a1[1]), add2(a1[2], a1[3])));
            float sc0 = r0.x + r0.y;
            float sc1 = r1.x + r1.y;

            float p0 = ((mb0 >> jj) & 1u) ? __expf(sc0) : 0.0f;
            float p1 = ((mb1 >> jj) & 1u) ? __expf(sc1) : 0.0f;
            l0 += p0;
            l1 += p1;
            ull pp0 = pack2(p0, p0);
            ull pp1 = pack2(p1, p1);

            const ulonglong2* vp = (const ulonglong2*)&sm_v[j * 32];
            #pragma unroll
            for (int d = 0; d < 8; d++) {
                ulonglong2 vv = vp[d];
                acc0[2 * d + 0] = fma2(pp0, vv.x, acc0[2 * d + 0]);
                acc0[2 * d + 1] = fma2(pp0, vv.y, acc0[2 * d + 1]);
                acc1[2 * d + 0] = fma2(pp1, vv.x, acc1[2 * d + 0]);
                acc1[2 * d + 1] = fma2(pp1, vv.y, acc1[2 * d + 1]);
            }
        }
    }

    const float inv0 = 1.0f / l0;
    const float inv1 = 1.0f / l1;
    const size_t orow0 = ((size_t)(s * B_DIM + b) * N_DIM + i0) * INNER + h * DHEAD;
    const size_t orow1 = ((size_t)(s * B_DIM + b) * N_DIM + i1) * INNER + h * DHEAD;
    #pragma unroll
    for (int d = 0; d < 8; d++) {
        float2 u0 = unpack2(acc0[2 * d + 0]);
        float2 u1 = unpack2(acc0[2 * d + 1]);
        *(float4*)(outp + orow0 + d * 4) =
            make_float4(u0.x * inv0, u0.y * inv0, u1.x * inv0, u1.y * inv0);
        float2 w0 = unpack2(acc1[2 * d + 0]);
        float2 w1 = unpack2(acc1[2 * d + 1]);
        *(float4*)(outp + orow1 + d * 4) =
            make_float4(w0.x * inv1, w0.y * inv1, w1.x * inv1, w1.y * inv1);
    }
}

// ---------------------------------------------------------------------------
// Launch
// ---------------------------------------------------------------------------
extern "C" void kernel_launch(void* const* d_in, const int* in_sizes, int n_in,
                              void* d_out, int out_size) {
    const float* x     = (const float*)d_in[0];
    const int*   mask  = (const int*)d_in[1];
    const float* Wqkv  = (const float*)d_in[2];
    const float* Wout  = (const float*)d_in[3];
    const float* bout  = (const float*)d_in[4];
    float* out = (float*)d_out;

    float* qkvbuf = nullptr;
    float* attnbuf = nullptr;
    cudaGetSymbolAddress((void**)&qkvbuf, g_qkv);
    cudaGetSymbolAddress((void**)&attnbuf, g_attn);

    cudaFuncSetAttribute(attn_kernel, cudaFuncAttributeMaxDynamicSharedMemorySize,
                         ATTN_SMEM_BYTES);

    // 0) Pre-pack mask bits (depends only on s; 64 tiny blocks)
    pack_mask_kernel<<<S_DIM, N_DIM>>>(mask);

    // 1) QKV projection: [65536,256] @ [256,768]
    {
        dim3 grid(QKV_COLS / BN, M_TOTAL / BM);
        sgemm_kernel<<<grid, 256>>>(x, Wqkv, nullptr, qkvbuf,
                                    M_TOTAL, QKV_COLS, D_MODEL);
    }
    // 2) Attention per (s,b,h): 128 threads, 2 query rows/thread
    {
        dim3 grid(HEADS, B_DIM, S_DIM);
        attn_kernel<<<grid, 128, ATTN_SMEM_BYTES>>>(qkvbuf, attnbuf);
    }
    // 3) Output projection: [65536,256] @ [256,256] + bias
    {
        dim3 grid(INNER / BN, M_TOTAL / BM);
        sgemm_kernel<<<grid, 256>>>(attnbuf, Wout, bout, out,
                                    M_TOTAL, D_MODEL, INNER);
    }
}

// round 8
// speedup vs baseline: 1.4993x; 1.4993x over previous
#include <cuda_runtime.h>
#include <cuda_bf16.h>
#include <cstdint>
#include <cstddef>

// Problem constants
#define S_DIM 64
#define B_DIM 4
#define N_DIM 256
#define D_MODEL 256
#define HEADS 8
#define DHEAD 32
#define INNER 256
#define QKV_COLS 768
#define M_TOTAL (S_DIM * B_DIM * N_DIM)   // 65536
#define SCALE 0.17677669529663687f
#define KP 768            // K' = 3*256 (hi/lo/hi split concat)
#define BKC 64            // bf16 per K chunk (128 B rows)
#define NCHUNKS 12        // KP / BKC

typedef unsigned long long ull;

// ---- packed f32x2 helpers (attention) ----
__device__ __forceinline__ ull fma2(ull a, ull b, ull c) {
    ull d; asm("fma.rn.f32x2 %0, %1, %2, %3;" : "=l"(d) : "l"(a), "l"(b), "l"(c));
    return d;
}
__device__ __forceinline__ ull add2(ull a, ull b) {
    ull d; asm("add.rn.f32x2 %0, %1, %2;" : "=l"(d) : "l"(a), "l"(b));
    return d;
}
__device__ __forceinline__ ull pack2(float lo, float hi) {
    ull d; asm("mov.b64 %0, {%1, %2};" : "=l"(d) : "f"(lo), "f"(hi));
    return d;
}
__device__ __forceinline__ float2 unpack2(ull v) {
    float lo, hi; asm("mov.b64 {%0, %1}, %2;" : "=f"(lo), "=f"(hi) : "l"(v));
    return make_float2(lo, hi);
}

// ---- mma / ldmatrix / cp.async helpers (baseline PTX, sm_80+) ----
__device__ __forceinline__ uint32_t smem_u32(const void* p) {
    uint32_t a;
    asm("{ .reg .u64 t; cvta.to.shared.u64 t, %1; cvt.u32.u64 %0, t; }"
        : "=r"(a) : "l"(p));
    return a;
}
__device__ __forceinline__ void ldm4(uint32_t* r, uint32_t addr) {
    asm volatile("ldmatrix.sync.aligned.m8n8.x4.shared.b16 {%0,%1,%2,%3}, [%4];"
        : "=r"(r[0]), "=r"(r[1]), "=r"(r[2]), "=r"(r[3]) : "r"(addr));
}
__device__ __forceinline__ void mma16816(float* c, const uint32_t* a,
                                         uint32_t b0, uint32_t b1) {
    asm volatile("mma.sync.aligned.m16n8k16.row.col.f32.bf16.bf16.f32 "
        "{%0,%1,%2,%3}, {%4,%5,%6,%7}, {%8,%9}, {%0,%1,%2,%3};"
        : "+f"(c[0]), "+f"(c[1]), "+f"(c[2]), "+f"(c[3])
        : "r"(a[0]), "r"(a[1]), "r"(a[2]), "r"(a[3]), "r"(b0), "r"(b1));
}
__device__ __forceinline__ void cp16(uint32_t s, const void* g) {
    asm volatile("cp.async.cg.shared.global [%0], [%1], 16;" :: "r"(s), "l"(g));
}
__device__ __forceinline__ void cp_commit() {
    asm volatile("cp.async.commit_group;" ::: "memory");
}
template <int N>
__device__ __forceinline__ void cp_wait() {
    asm volatile("cp.async.wait_group %0;" :: "n"(N) : "memory");
}

// Scratch (allocation-free rule: __device__ globals)
__device__ float g_qkv[(size_t)M_TOTAL * QKV_COLS];            // 192 MB
__device__ float g_attn[(size_t)M_TOTAL * INNER];              // 64 MB
__device__ __nv_bfloat16 g_abf[(size_t)M_TOTAL * KP];          // 100 MB (split A)
__device__ __nv_bfloat16 g_wqt[(size_t)QKV_COLS * KP];         // W_qkv^T split
__device__ __nv_bfloat16 g_wot[(size_t)D_MODEL * KP];          // W_out^T split
__device__ unsigned g_maskpack[S_DIM][N_DIM][8];

// ---------------------------------------------------------------------------
// Prep kernels
// ---------------------------------------------------------------------------
__global__ void pack_mask_kernel(const int* __restrict__ mask) {
    const int s = blockIdx.x, i = threadIdx.x;
    const int* p = mask + ((size_t)s * N_DIM + i) * N_DIM;
    #pragma unroll
    for (int c = 0; c < 8; c++) {
        unsigned bits = 0;
        #pragma unroll 8
        for (int bb = 0; bb < 32; bb++)
            bits |= (unsigned)(p[c * 32 + bb] != 0) << bb;
        g_maskpack[s][i][c] = bits;
    }
}

// split fp32 [rows,256] -> bf16 [rows,768] as [hi, lo, hi]
__global__ void split_a_kernel(const float* __restrict__ src,
                               __nv_bfloat16* __restrict__ dst) {
    const size_t row = blockIdx.x;
    const int col = threadIdx.x;
    float x = src[row * 256 + col];
    __nv_bfloat16 hi = __float2bfloat16_rn(x);
    __nv_bfloat16 lo = __float2bfloat16_rn(x - __bfloat162float(hi));
    __nv_bfloat16* d = dst + row * KP;
    d[col] = hi; d[256 + col] = lo; d[512 + col] = hi;
}

// W [256 (k), Ncols] fp32 -> Wt bf16 [Ncols (n)][768] as [hi, hi, lo]
__global__ void split_w_kernel(const float* __restrict__ W,
                               __nv_bfloat16* __restrict__ Wt, int Ncols) {
    const int n = blockIdx.x;
    const int k = threadIdx.x;
    float w = W[(size_t)k * Ncols + n];
    __nv_bfloat16 hi = __float2bfloat16_rn(w);
    __nv_bfloat16 lo = __float2bfloat16_rn(w - __bfloat162float(hi));
    __nv_bfloat16* d = Wt + (size_t)n * KP;
    d[k] = hi; d[256 + k] = hi; d[512 + k] = lo;
}

// ---------------------------------------------------------------------------
// Tensor-core GEMM (mma.sync bf16): C[M,Ntot] = A'[M,768] x Bt'[Ntot,768]^T
// 128x128 CTA tile, 8 warps (32x64 each), cp.async double-buffered BK=64.
// SMEM: A0 A1 B0 B1, 16 KB each (swizzled 128B rows).
// ---------------------------------------------------------------------------
#define GEMM_SMEM (64 * 1024)

__global__ __launch_bounds__(256, 2)
void gemm_mma_kernel(const __nv_bfloat16* __restrict__ A,
                     const __nv_bfloat16* __restrict__ Bt,
                     float* __restrict__ C, const float* __restrict__ bias,
                     int Ntot) {
    extern __shared__ __align__(1024) char smx[];
    const uint32_t sb = smem_u32(smx);
    const int tid = threadIdx.x;
    const int lane = tid & 31, w = tid >> 5;
    const int bx = blockIdx.x, by = blockIdx.y;
    const size_t arow0 = (size_t)by * 128;
    const size_t brow0 = (size_t)bx * 128;
    const int mrow = (w & 3) * 32;       // warp M offset in tile
    const int ncol = (w >> 2) * 64;      // warp N offset in tile

    // ldmatrix lane base offsets (swizzled row part; k-bytes XORed in later)
    uint32_t aoff[2], boff[4];
    const uint32_t khA = (lane >> 4) * 16;              // A k-half (16B)
    const uint32_t khB = ((lane >> 3) & 1) * 16;        // B k-half (16B)
    #pragma unroll
    for (int mt = 0; mt < 2; mt++) {
        uint32_t rp = (uint32_t)(mrow + mt * 16 + (lane & 15)) * 128;
        aoff[mt] = rp ^ ((rp >> 3) & 0x70);
    }
    #pragma unroll
    for (int nt = 0; nt < 4; nt++) {
        uint32_t n = ncol + nt * 16 + (lane & 7) + ((lane >> 4) << 3);
        uint32_t rp = n * 128;
        boff[nt] = rp ^ ((rp >> 3) & 0x70);
    }

    const char* Abase = (const char*)(A + arow0 * KP);
    const char* Bbase = (const char*)(Bt + brow0 * KP);
    // gmem/smem cp.async lane mapping: 8 16B parts per 128B row
    const int crow = tid >> 1;            // 0..127 (2 threads per row)
    const int cpart = (tid & 1) * 4;      // parts 0-3 or 4-7

    float acc[2][8][4];
    #pragma unroll
    for (int mt = 0; mt < 2; mt++)
        #pragma unroll
        for (int nt = 0; nt < 8; nt++)
            #pragma unroll
            for (int q = 0; q < 4; q++) acc[mt][nt][q] = 0.0f;

    // chunk issue: A&B 128 rows x 128B each; 256 thr x (4+4) cp.async
    auto issue = [&](int c, int buf) {
        const char* Ac = Abase + c * 128;
        const char* Bc = Bbase + c * 128;
        uint32_t sA = sb + buf * 16384;
        uint32_t sB = sb + 32768 + buf * 16384;
        #pragma unroll
        for (int p = 0; p < 4; p++) {
            uint32_t off = (uint32_t)crow * 128 + (cpart + p) * 16;
            uint32_t sw = off ^ ((off >> 3) & 0x70);
            cp16(sA + sw, Ac + (size_t)crow * (KP * 2) + (cpart + p) * 16);
            cp16(sB + sw, Bc + (size_t)crow * (KP * 2) + (cpart + p) * 16);
        }
        cp_commit();
    };

    issue(0, 0);
    for (int c = 0; c < NCHUNKS; c++) {
        const int buf = c & 1;
        if (c + 1 < NCHUNKS) {
            issue(c + 1, buf ^ 1);
            cp_wait<1>();
        } else {
            cp_wait<0>();
        }
        __syncthreads();

        const uint32_t sA = sb + buf * 16384;
        const uint32_t sB = sb + 32768 + buf * 16384;
        #pragma unroll
        for (int ks = 0; ks < 4; ks++) {
            uint32_t a[2][4], b[4][4];
            #pragma unroll
            for (int mt = 0; mt < 2; mt++)
                ldm4(a[mt], sA + (aoff[mt] ^ (ks * 32 + khA)));
            #pragma unroll
            for (int nt = 0; nt < 4; nt++)
                ldm4(b[nt], sB + (boff[nt] ^ (ks * 32 + khB)));
            #pragma unroll
            for (int mt = 0; mt < 2; mt++)
                #pragma unroll
                for (int nt = 0; nt < 4; nt++) {
                    mma16816(acc[mt][2 * nt + 0], a[mt], b[nt][0], b[nt][1]);
                    mma16816(acc[mt][2 * nt + 1], a[mt], b[nt][2], b[nt][3]);
                }
        }
        __syncthreads();
    }

    // Epilogue: direct float2 stores (+bias)
    const int g = lane >> 2, t4 = lane & 3;
    #pragma unroll
    for (int mt = 0; mt < 2; mt++) {
        #pragma unroll
        for (int sub = 0; sub < 2; sub++) {
            size_t row = arow0 + mrow + mt * 16 + g + sub * 8;
            float* Cr = C + row * Ntot + brow0;
            #pragma unroll
            for (int nt = 0; nt < 8; nt++) {
                int col = ncol + nt * 8 + 2 * t4;
                float2 v = make_float2(acc[mt][nt][sub * 2 + 0],
                                       acc[mt][nt][sub * 2 + 1]);
                if (bias) {
                    v.x += __ldg(bias + brow0 + col);
                    v.y += __ldg(bias + brow0 + col + 1);
                }
                *(float2*)(Cr + col) = v;
            }
        }
    }
}

// ---------------------------------------------------------------------------
// Attention (R5, measured-good): 128 thr/block, 2 query rows/thread.
// ---------------------------------------------------------------------------
#define ATTN_SMEM_BYTES ((256 * 32 + 256 * 32) * 4)

__global__ __launch_bounds__(128, 2)
void attn_kernel(const float* __restrict__ qkv, float* __restrict__ outp) {
    extern __shared__ float sm[];
    float* sm_k = sm;
    float* sm_v = sm_k + 256 * 32;

    const int tid = threadIdx.x;
    const int h = blockIdx.x, b = blockIdx.y, s = blockIdx.z;

    const size_t base = ((size_t)(s * B_DIM + b) * N_DIM) * QKV_COLS;
    const int qoff = h * DHEAD;
    const int koff = INNER + h * DHEAD;
    const int voff = 2 * INNER + h * DHEAD;

    for (int idx = tid; idx < 256 * 8; idx += 128) {
        int j = idx >> 3, d4 = (idx & 7) * 4;
        const float* rowp = qkv + base + (size_t)j * QKV_COLS;
        *(float4*)&sm_k[j * 32 + d4] = *(const float4*)(rowp + koff + d4);
        *(float4*)&sm_v[j * 32 + d4] = *(const float4*)(rowp + voff + d4);
    }

    const int i0 = tid, i1 = tid + 128;
    ull q0p[16], q1p[16];
    {
        const float* q0 = qkv + base + (size_t)i0 * QKV_COLS + qoff;
        const float* q1 = qkv + base + (size_t)i1 * QKV_COLS + qoff;
        #pragma unroll
        for (int d4 = 0; d4 < 8; d4++) {
            float4 t0 = *(const float4*)(q0 + d4 * 4);
            float4 t1 = *(const float4*)(q1 + d4 * 4);
            q0p[2 * d4 + 0] = pack2(t0.x * SCALE, t0.y * SCALE);
            q0p[2 * d4 + 1] = pack2(t0.z * SCALE, t0.w * SCALE);
            q1p[2 * d4 + 0] = pack2(t1.x * SCALE, t1.y * SCALE);
            q1p[2 * d4 + 1] = pack2(t1.z * SCALE, t1.w * SCALE);
        }
    }
    __syncthreads();

    ull acc0[16], acc1[16];
    #pragma unroll
    for (int d = 0; d < 16; d++) { acc0[d] = 0ull; acc1[d] = 0ull; }
    float l0 = 0.0f, l1 = 0.0f;

    for (int jw = 0; jw < 8; jw++) {
        const unsigned mb0 = g_maskpack[s][i0][jw];
        const unsigned mb1 = g_maskpack[s][i1][jw];
        #pragma unroll 2
        for (int jj = 0; jj < 32; jj++) {
            const int j = jw * 32 + jj;
            const ulonglong2* kp = (const ulonglong2*)&sm_k[j * 32];
            ull a0[4] = {0ull, 0ull, 0ull, 0ull};
            ull a1[4] = {0ull, 0ull, 0ull, 0ull};
            #pragma unroll
            for (int d = 0; d < 8; d++) {
                ulonglong2 kk = kp[d];
                a0[(2 * d + 0) & 3] = fma2(q0p[2 * d + 0], kk.x, a0[(2 * d + 0) & 3]);
                a0[(2 * d + 1) & 3] = fma2(q0p[2 * d + 1], kk.y, a0[(2 * d + 1) & 3]);
                a1[(2 * d + 0) & 3] = fma2(q1p[2 * d + 0], kk.x, a1[(2 * d + 0) & 3]);
                a1[(2 * d + 1) & 3] = fma2(q1p[2 * d + 1], kk.y, a1[(2 * d + 1) & 3]);
            }
            float2 r0 = unpack2(add2(add2(a0[0], a0[1]), add2(a0[2], a0[3])));
            float2 r1 = unpack2(add2(add2(a1[0], a1[1]), add2(a1[2], a1[3])));
            float sc0 = r0.x + r0.y;
            float sc1 = r1.x + r1.y;

            float p0 = ((mb0 >> jj) & 1u) ? __expf(sc0) : 0.0f;
            float p1 = ((mb1 >> jj) & 1u) ? __expf(sc1) : 0.0f;
            l0 += p0; l1 += p1;
            ull pp0 = pack2(p0, p0);
            ull pp1 = pack2(p1, p1);

            const ulonglong2* vp = (const ulonglong2*)&sm_v[j * 32];
            #pragma unroll
            for (int d = 0; d < 8; d++) {
                ulonglong2 vv = vp[d];
                acc0[2 * d + 0] = fma2(pp0, vv.x, acc0[2 * d + 0]);
                acc0[2 * d + 1] = fma2(pp0, vv.y, acc0[2 * d + 1]);
                acc1[2 * d + 0] = fma2(pp1, vv.x, acc1[2 * d + 0]);
                acc1[2 * d + 1] = fma2(pp1, vv.y, acc1[2 * d + 1]);
            }
        }
    }

    const float inv0 = 1.0f / l0;
    const float inv1 = 1.0f / l1;
    const size_t orow0 = ((size_t)(s * B_DIM + b) * N_DIM + i0) * INNER + h * DHEAD;
    const size_t orow1 = ((size_t)(s * B_DIM + b) * N_DIM + i1) * INNER + h * DHEAD;
    #pragma unroll
    for (int d = 0; d < 8; d++) {
        float2 u0 = unpack2(acc0[2 * d + 0]);
        float2 u1 = unpack2(acc0[2 * d + 1]);
        *(float4*)(outp + orow0 + d * 4) =
            make_float4(u0.x * inv0, u0.y * inv0, u1.x * inv0, u1.y * inv0);
        float2 w0 = unpack2(acc1[2 * d + 0]);
        float2 w1 = unpack2(acc1[2 * d + 1]);
        *(float4*)(outp + orow1 + d * 4) =
            make_float4(w0.x * inv1, w0.y * inv1, w1.x * inv1, w1.y * inv1);
    }
}

// ---------------------------------------------------------------------------
// Launch
// ---------------------------------------------------------------------------
extern "C" void kernel_launch(void* const* d_in, const int* in_sizes, int n_in,
                              void* d_out, int out_size) {
    const float* x    = (const float*)d_in[0];
    const int*   mask = (const int*)d_in[1];
    const float* Wqkv = (const float*)d_in[2];
    const float* Wout = (const float*)d_in[3];
    const float* bout = (const float*)d_in[4];
    float* out = (float*)d_out;

    float *qkvbuf = nullptr, *attnbuf = nullptr;
    __nv_bfloat16 *abf = nullptr, *wqt = nullptr, *wot = nullptr;
    cudaGetSymbolAddress((void**)&qkvbuf, g_qkv);
    cudaGetSymbolAddress((void**)&attnbuf, g_attn);
    cudaGetSymbolAddress((void**)&abf, g_abf);
    cudaGetSymbolAddress((void**)&wqt, g_wqt);
    cudaGetSymbolAddress((void**)&wot, g_wot);

    cudaFuncSetAttribute(attn_kernel, cudaFuncAttributeMaxDynamicSharedMemorySize,
                         ATTN_SMEM_BYTES);
    cudaFuncSetAttribute(gemm_mma_kernel, cudaFuncAttributeMaxDynamicSharedMemorySize,
                         GEMM_SMEM);

    // Prep
    pack_mask_kernel<<<S_DIM, N_DIM>>>(mask);
    split_w_kernel<<<QKV_COLS, 256>>>(Wqkv, wqt, QKV_COLS);
    split_w_kernel<<<D_MODEL, 256>>>(Wout, wot, D_MODEL);
    split_a_kernel<<<M_TOTAL, 256>>>(x, abf);

    // 1) QKV projection (tensor cores)
    {
        dim3 grid(QKV_COLS / 128, M_TOTAL / 128);
        gemm_mma_kernel<<<grid, 256, GEMM_SMEM>>>(abf, wqt, qkvbuf, nullptr,
                                                  QKV_COLS);
    }
    // 2) Attention
    {
        dim3 grid(HEADS, B_DIM, S_DIM);
        attn_kernel<<<grid, 128, ATTN_SMEM_BYTES>>>(qkvbuf, attnbuf);
    }
    // 3) Output projection: split attn output, then MMA GEMM + bias
    split_a_kernel<<<M_TOTAL, 256>>>(attnbuf, abf);
    {
        dim3 grid(D_MODEL / 128, M_TOTAL / 128);
        gemm_mma_kernel<<<grid, 256, GEMM_SMEM>>>(abf, wot, out, bout,
                                                  D_MODEL);
    }
}

// round 9
// speedup vs baseline: 1.5592x; 1.0399x over previous
#include <cuda_runtime.h>
#include <cuda_bf16.h>
#include <cstdint>
#include <cstddef>

// Problem constants
#define S_DIM 64
#define B_DIM 4
#define N_DIM 256
#define D_MODEL 256
#define HEADS 8
#define DHEAD 32
#define INNER 256
#define QKV_COLS 768
#define M_TOTAL (S_DIM * B_DIM * N_DIM)   // 65536
#define SCALE 0.17677669529663687f
#define KS 512            // stored split width: [hi(256) | lo(256)]
#define NCHUNKS 12        // logical K' = 768 = 12 x 64

typedef unsigned long long ull;

// ---- packed f32x2 helpers (attention) ----
__device__ __forceinline__ ull fma2(ull a, ull b, ull c) {
    ull d; asm("fma.rn.f32x2 %0, %1, %2, %3;" : "=l"(d) : "l"(a), "l"(b), "l"(c));
    return d;
}
__device__ __forceinline__ ull add2(ull a, ull b) {
    ull d; asm("add.rn.f32x2 %0, %1, %2;" : "=l"(d) : "l"(a), "l"(b));
    return d;
}
__device__ __forceinline__ ull pack2(float lo, float hi) {
    ull d; asm("mov.b64 %0, {%1, %2};" : "=l"(d) : "f"(lo), "f"(hi));
    return d;
}
__device__ __forceinline__ float2 unpack2(ull v) {
    float lo, hi; asm("mov.b64 {%0, %1}, %2;" : "=f"(lo), "=f"(hi) : "l"(v));
    return make_float2(lo, hi);
}

// ---- mma / ldmatrix / cp.async helpers (baseline PTX, sm_80+) ----
__device__ __forceinline__ uint32_t smem_u32(const void* p) {
    uint32_t a;
    asm("{ .reg .u64 t; cvta.to.shared.u64 t, %1; cvt.u32.u64 %0, t; }"
        : "=r"(a) : "l"(p));
    return a;
}
__device__ __forceinline__ void ldm4(uint32_t* r, uint32_t addr) {
    asm volatile("ldmatrix.sync.aligned.m8n8.x4.shared.b16 {%0,%1,%2,%3}, [%4];"
        : "=r"(r[0]), "=r"(r[1]), "=r"(r[2]), "=r"(r[3]) : "r"(addr));
}
__device__ __forceinline__ void mma16816(float* c, const uint32_t* a,
                                         uint32_t b0, uint32_t b1) {
    asm volatile("mma.sync.aligned.m16n8k16.row.col.f32.bf16.bf16.f32 "
        "{%0,%1,%2,%3}, {%4,%5,%6,%7}, {%8,%9}, {%0,%1,%2,%3};"
        : "+f"(c[0]), "+f"(c[1]), "+f"(c[2]), "+f"(c[3])
        : "r"(a[0]), "r"(a[1]), "r"(a[2]), "r"(a[3]), "r"(b0), "r"(b1));
}
__device__ __forceinline__ void cp16(uint32_t s, const void* g) {
    asm volatile("cp.async.cg.shared.global [%0], [%1], 16;" :: "r"(s), "l"(g));
}
__device__ __forceinline__ void cp_commit() {
    asm volatile("cp.async.commit_group;" ::: "memory");
}
template <int N>
__device__ __forceinline__ void cp_wait() {
    asm volatile("cp.async.wait_group %0;" :: "n"(N) : "memory");
}

// Scratch (allocation-free rule: __device__ globals)
__device__ float g_qkv[(size_t)M_TOTAL * QKV_COLS];            // 192 MB
__device__ __nv_bfloat16 g_abf[(size_t)M_TOTAL * KS];          // 67 MB (split A)
__device__ __nv_bfloat16 g_wqt[(size_t)QKV_COLS * KS];         // W_qkv^T split
__device__ __nv_bfloat16 g_wot[(size_t)D_MODEL * KS];          // W_out^T split
__device__ unsigned g_maskpack[S_DIM][N_DIM][8];

// ---------------------------------------------------------------------------
// Prep kernels
// ---------------------------------------------------------------------------
__global__ void pack_mask_kernel(const int* __restrict__ mask) {
    const int s = blockIdx.x, i = threadIdx.x;
    const int* p = mask + ((size_t)s * N_DIM + i) * N_DIM;
    #pragma unroll
    for (int c = 0; c < 8; c++) {
        unsigned bits = 0;
        #pragma unroll 8
        for (int bb = 0; bb < 32; bb++)
            bits |= (unsigned)(p[c * 32 + bb] != 0) << bb;
        g_maskpack[s][i][c] = bits;
    }
}

// split fp32 [rows,256] -> bf16 [rows,512] as [hi | lo]
__global__ void split_a_kernel(const float* __restrict__ src,
                               __nv_bfloat16* __restrict__ dst) {
    const size_t row = blockIdx.x;
    const int col = threadIdx.x;
    float x = src[row * 256 + col];
    __nv_bfloat16 hi = __float2bfloat16_rn(x);
    __nv_bfloat16 lo = __float2bfloat16_rn(x - __bfloat162float(hi));
    __nv_bfloat16* d = dst + row * KS;
    d[col] = hi; d[256 + col] = lo;
}

// W [256 (k), Ncols] fp32 -> Wt bf16 [Ncols (n)][512] as [hi | lo]
__global__ void split_w_kernel(const float* __restrict__ W,
                               __nv_bfloat16* __restrict__ Wt, int Ncols) {
    const int n = blockIdx.x;
    const int k = threadIdx.x;
    float w = W[(size_t)k * Ncols + n];
    __nv_bfloat16 hi = __float2bfloat16_rn(w);
    __nv_bfloat16 lo = __float2bfloat16_rn(w - __bfloat162float(hi));
    __nv_bfloat16* d = Wt + (size_t)n * KS;
    d[k] = hi; d[256 + k] = lo;
}

// ---------------------------------------------------------------------------
// Tensor-core GEMM (mma.sync bf16): C = A' x B'^T with logical K' = 768
// realized as 12 chunks; chunk c uses A chunk cmapA[c], B chunk cmapB[c]
// so that products run hi*hi (c0-3), lo*hi (c4-7), hi*lo (c8-11).
// 128x128 CTA tile, 8 warps (32x64 each), cp.async double-buffered.
// ---------------------------------------------------------------------------
#define GEMM_SMEM (64 * 1024)

__constant__ int c_cmapA[NCHUNKS] = {0,1,2,3,4,5,6,7,0,1,2,3};
__constant__ int c_cmapB[NCHUNKS] = {0,1,2,3,0,1,2,3,4,5,6,7};

__global__ __launch_bounds__(256, 2)
void gemm_mma_kernel(const __nv_bfloat16* __restrict__ A,
                     const __nv_bfloat16* __restrict__ Bt,
                     float* __restrict__ C, const float* __restrict__ bias,
                     int Ntot) {
    extern __shared__ __align__(1024) char smx[];
    const uint32_t sb = smem_u32(smx);
    const int tid = threadIdx.x;
    const int lane = tid & 31, w = tid >> 5;
    const int bx = blockIdx.x, by = blockIdx.y;
    const size_t arow0 = (size_t)by * 128;
    const size_t brow0 = (size_t)bx * 128;
    const int mrow = (w & 3) * 32;
    const int ncol = (w >> 2) * 64;

    uint32_t aoff[2], boff[4];
    const uint32_t khA = (lane >> 4) * 16;
    const uint32_t khB = ((lane >> 3) & 1) * 16;
    #pragma unroll
    for (int mt = 0; mt < 2; mt++) {
        uint32_t rp = (uint32_t)(mrow + mt * 16 + (lane & 15)) * 128;
        aoff[mt] = rp ^ ((rp >> 3) & 0x70);
    }
    #pragma unroll
    for (int nt = 0; nt < 4; nt++) {
        uint32_t n = ncol + nt * 16 + (lane & 7) + ((lane >> 4) << 3);
        uint32_t rp = n * 128;
        boff[nt] = rp ^ ((rp >> 3) & 0x70);
    }

    const char* Abase = (const char*)(A + arow0 * KS);
    const char* Bbase = (const char*)(Bt + brow0 * KS);
    const int crow = tid >> 1;
    const int cpart = (tid & 1) * 4;

    float acc[2][8][4];
    #pragma unroll
    for (int mt = 0; mt < 2; mt++)
        #pragma unroll
        for (int nt = 0; nt < 8; nt++)
            #pragma unroll
            for (int q = 0; q < 4; q++) acc[mt][nt][q] = 0.0f;

    auto issue = [&](int c, int buf) {
        const char* Ac = Abase + c_cmapA[c] * 128;
        const char* Bc = Bbase + c_cmapB[c] * 128;
        uint32_t sA = sb + buf * 16384;
        uint32_t sB = sb + 32768 + buf * 16384;
        #pragma unroll
        for (int p = 0; p < 4; p++) {
            uint32_t off = (uint32_t)crow * 128 + (cpart + p) * 16;
            uint32_t sw = off ^ ((off >> 3) & 0x70);
            cp16(sA + sw, Ac + (size_t)crow * (KS * 2) + (cpart + p) * 16);
            cp16(sB + sw, Bc + (size_t)crow * (KS * 2) + (cpart + p) * 16);
        }
        cp_commit();
    };

    issue(0, 0);
    for (int c = 0; c < NCHUNKS; c++) {
        const int buf = c & 1;
        if (c + 1 < NCHUNKS) {
            issue(c + 1, buf ^ 1);
            cp_wait<1>();
        } else {
            cp_wait<0>();
        }
        __syncthreads();

        const uint32_t sA = sb + buf * 16384;
        const uint32_t sB = sb + 32768 + buf * 16384;
        #pragma unroll
        for (int ks = 0; ks < 4; ks++) {
            uint32_t a[2][4], b[4][4];
            #pragma unroll
            for (int mt = 0; mt < 2; mt++)
                ldm4(a[mt], sA + (aoff[mt] ^ (ks * 32 + khA)));
            #pragma unroll
            for (int nt = 0; nt < 4; nt++)
                ldm4(b[nt], sB + (boff[nt] ^ (ks * 32 + khB)));
            #pragma unroll
            for (int mt = 0; mt < 2; mt++)
                #pragma unroll
                for (int nt = 0; nt < 4; nt++) {
                    mma16816(acc[mt][2 * nt + 0], a[mt], b[nt][0], b[nt][1]);
                    mma16816(acc[mt][2 * nt + 1], a[mt], b[nt][2], b[nt][3]);
                }
        }
        __syncthreads();
    }

    // Epilogue: direct float2 stores (+bias)
    const int g = lane >> 2, t4 = lane & 3;
    #pragma unroll
    for (int mt = 0; mt < 2; mt++) {
        #pragma unroll
        for (int sub = 0; sub < 2; sub++) {
            size_t row = arow0 + mrow + mt * 16 + g + sub * 8;
            float* Cr = C + row * Ntot + brow0;
            #pragma unroll
            for (int nt = 0; nt < 8; nt++) {
                int col = ncol + nt * 8 + 2 * t4;
                float2 v = make_float2(acc[mt][nt][sub * 2 + 0],
                                       acc[mt][nt][sub * 2 + 1]);
                if (bias) {
                    v.x += __ldg(bias + brow0 + col);
                    v.y += __ldg(bias + brow0 + col + 1);
                }
                *(float2*)(Cr + col) = v;
            }
        }
    }
}

// ---------------------------------------------------------------------------
// Attention: 128 thr/block, 2 query rows/thread, 3 CTAs/SM.
// Epilogue writes hi/lo split bf16 directly into g_abf (fuses the split).
// ---------------------------------------------------------------------------
#define ATTN_SMEM_BYTES ((256 * 32 + 256 * 32) * 4)

__global__ __launch_bounds__(128, 3)
void attn_kernel(const float* __restrict__ qkv, __nv_bfloat16* __restrict__ outsp) {
    extern __shared__ float sm[];
    float* sm_k = sm;
    float* sm_v = sm_k + 256 * 32;

    const int tid = threadIdx.x;
    const int h = blockIdx.x, b = blockIdx.y, s = blockIdx.z;

    const size_t base = ((size_t)(s * B_DIM + b) * N_DIM) * QKV_COLS;
    const int qoff = h * DHEAD;
    const int koff = INNER + h * DHEAD;
    const int voff = 2 * INNER + h * DHEAD;

    for (int idx = tid; idx < 256 * 8; idx += 128) {
        int j = idx >> 3, d4 = (idx & 7) * 4;
        const float* rowp = qkv + base + (size_t)j * QKV_COLS;
        *(float4*)&sm_k[j * 32 + d4] = *(const float4*)(rowp + koff + d4);
        *(float4*)&sm_v[j * 32 + d4] = *(const float4*)(rowp + voff + d4);
    }

    const int i0 = tid, i1 = tid + 128;
    ull q0p[16], q1p[16];
    {
        const float* q0 = qkv + base + (size_t)i0 * QKV_COLS + qoff;
        const float* q1 = qkv + base + (size_t)i1 * QKV_COLS + qoff;
        #pragma unroll
        for (int d4 = 0; d4 < 8; d4++) {
            float4 t0 = *(const float4*)(q0 + d4 * 4);
            float4 t1 = *(const float4*)(q1 + d4 * 4);
            q0p[2 * d4 + 0] = pack2(t0.x * SCALE, t0.y * SCALE);
            q0p[2 * d4 + 1] = pack2(t0.z * SCALE, t0.w * SCALE);
            q1p[2 * d4 + 0] = pack2(t1.x * SCALE, t1.y * SCALE);
            q1p[2 * d4 + 1] = pack2(t1.z * SCALE, t1.w * SCALE);
        }
    }
    __syncthreads();

    ull acc0[16], acc1[16];
    #pragma unroll
    for (int d = 0; d < 16; d++) { acc0[d] = 0ull; acc1[d] = 0ull; }
    float l0 = 0.0f, l1 = 0.0f;

    for (int jw = 0; jw < 8; jw++) {
        const unsigned mb0 = g_maskpack[s][i0][jw];
        const unsigned mb1 = g_maskpack[s][i1][jw];
        #pragma unroll 2
        for (int jj = 0; jj < 32; jj++) {
            const int j = jw * 32 + jj;
            const ulonglong2* kp = (const ulonglong2*)&sm_k[j * 32];
            ull a0[4] = {0ull, 0ull, 0ull, 0ull};
            ull a1[4] = {0ull, 0ull, 0ull, 0ull};
            #pragma unroll
            for (int d = 0; d < 8; d++) {
                ulonglong2 kk = kp[d];
                a0[(2 * d + 0) & 3] = fma2(q0p[2 * d + 0], kk.x, a0[(2 * d + 0) & 3]);
                a0[(2 * d + 1) & 3] = fma2(q0p[2 * d + 1], kk.y, a0[(2 * d + 1) & 3]);
                a1[(2 * d + 0) & 3] = fma2(q1p[2 * d + 0], kk.x, a1[(2 * d + 0) & 3]);
                a1[(2 * d + 1) & 3] = fma2(q1p[2 * d + 1], kk.y, a1[(2 * d + 1) & 3]);
            }
            float2 r0 = unpack2(add2(add2(a0[0], a0[1]), add2(a0[2], a0[3])));
            float2 r1 = unpack2(add2(add2(a1[0], a1[1]), add2(a1[2], a1[3])));
            float sc0 = r0.x + r0.y;
            float sc1 = r1.x + r1.y;

            float p0 = ((mb0 >> jj) & 1u) ? __expf(sc0) : 0.0f;
            float p1 = ((mb1 >> jj) & 1u) ? __expf(sc1) : 0.0f;
            l0 += p0; l1 += p1;
            ull pp0 = pack2(p0, p0);
            ull pp1 = pack2(p1, p1);

            const ulonglong2* vp = (const ulonglong2*)&sm_v[j * 32];
            #pragma unroll
            for (int d = 0; d < 8; d++) {
                ulonglong2 vv = vp[d];
                acc0[2 * d + 0] = fma2(pp0, vv.x, acc0[2 * d + 0]);
                acc0[2 * d + 1] = fma2(pp0, vv.y, acc0[2 * d + 1]);
                acc1[2 * d + 0] = fma2(pp1, vv.x, acc1[2 * d + 0]);
                acc1[2 * d + 1] = fma2(pp1, vv.y, acc1[2 * d + 1]);
            }
        }
    }

    // Epilogue: normalize, split to hi/lo bf16, write [row][hi(256)|lo(256)]
    const float inv0 = 1.0f / l0;
    const float inv1 = 1.0f / l1;
    const size_t r0 = (size_t)(s * B_DIM + b) * N_DIM + i0;
    const size_t r1 = (size_t)(s * B_DIM + b) * N_DIM + i1;
    __nv_bfloat16* o0 = outsp + r0 * KS + h * DHEAD;
    __nv_bfloat16* o1 = outsp + r1 * KS + h * DHEAD;
    float v0[32], v1[32];
    #pragma unroll
    for (int d = 0; d < 8; d++) {
        float2 u0 = unpack2(acc0[2 * d + 0]);
        float2 u1 = unpack2(acc0[2 * d + 1]);
        v0[4 * d + 0] = u0.x * inv0; v0[4 * d + 1] = u0.y * inv0;
        v0[4 * d + 2] = u1.x * inv0; v0[4 * d + 3] = u1.y * inv0;
        float2 w0 = unpack2(acc1[2 * d + 0]);
        float2 w1 = unpack2(acc1[2 * d + 1]);
        v1[4 * d + 0] = w0.x * inv1; v1[4 * d + 1] = w0.y * inv1;
        v1[4 * d + 2] = w1.x * inv1; v1[4 * d + 3] = w1.y * inv1;
    }
    #pragma unroll
    for (int g8 = 0; g8 < 4; g8++) {
        __nv_bfloat16 hi0[8], lo0[8], hi1[8], lo1[8];
        #pragma unroll
        for (int e = 0; e < 8; e++) {
            float x0 = v0[g8 * 8 + e];
            hi0[e] = __float2bfloat16_rn(x0);
            lo0[e] = __float2bfloat16_rn(x0 - __bfloat162float(hi0[e]));
            float x1 = v1[g8 * 8 + e];
            hi1[e] = __float2bfloat16_rn(x1);
            lo1[e] = __float2bfloat16_rn(x1 - __bfloat162float(hi1[e]));
        }
        *(uint4*)(o0 + g8 * 8) = *(const uint4*)hi0;
        *(uint4*)(o0 + 256 + g8 * 8) = *(const uint4*)lo0;
        *(uint4*)(o1 + g8 * 8) = *(const uint4*)hi1;
        *(uint4*)(o1 + 256 + g8 * 8) = *(const uint4*)lo1;
    }
}

// ---------------------------------------------------------------------------
// Launch
// ---------------------------------------------------------------------------
extern "C" void kernel_launch(void* const* d_in, const int* in_sizes, int n_in,
                              void* d_out, int out_size) {
    const float* x    = (const float*)d_in[0];
    const int*   mask = (const int*)d_in[1];
    const float* Wqkv = (const float*)d_in[2];
    const float* Wout = (const float*)d_in[3];
    const float* bout = (const float*)d_in[4];
    float* out = (float*)d_out;

    float* qkvbuf = nullptr;
    __nv_bfloat16 *abf = nullptr, *wqt = nullptr, *wot = nullptr;
    cudaGetSymbolAddress((void**)&qkvbuf, g_qkv);
    cudaGetSymbolAddress((void**)&abf, g_abf);
    cudaGetSymbolAddress((void**)&wqt, g_wqt);
    cudaGetSymbolAddress((void**)&wot, g_wot);

    cudaFuncSetAttribute(attn_kernel, cudaFuncAttributeMaxDynamicSharedMemorySize,
                         ATTN_SMEM_BYTES);
    cudaFuncSetAttribute(gemm_mma_kernel, cudaFuncAttributeMaxDynamicSharedMemorySize,
                         GEMM_SMEM);

    // Prep
    pack_mask_kernel<<<S_DIM, N_DIM>>>(mask);
    split_w_kernel<<<QKV_COLS, 256>>>(Wqkv, wqt, QKV_COLS);
    split_w_kernel<<<D_MODEL, 256>>>(Wout, wot, D_MODEL);
    split_a_kernel<<<M_TOTAL, 256>>>(x, abf);

    // 1) QKV projection (tensor cores)
    {
        dim3 grid(QKV_COLS / 128, M_TOTAL / 128);
        gemm_mma_kernel<<<grid, 256, GEMM_SMEM>>>(abf, wqt, qkvbuf, nullptr,
                                                  QKV_COLS);
    }
    // 2) Attention (writes split bf16 output directly)
    {
        dim3 grid(HEADS, B_DIM, S_DIM);
        attn_kernel<<<grid, 128, ATTN_SMEM_BYTES>>>(qkvbuf, abf);
    }
    // 3) Output projection (reads fused-split attn output)
    {
        dim3 grid(D_MODEL / 128, M_TOTAL / 128);
        gemm_mma_kernel<<<grid, 256, GEMM_SMEM>>>(abf, wot, out, bout,
                                                  D_MODEL);
    }
}

// round 11
// speedup vs baseline: 2.0688x; 1.3268x over previous
#include <cuda_runtime.h>
#include <cuda_bf16.h>
#include <cstdint>
#include <cstddef>

// Problem constants
#define S_DIM 64
#define B_DIM 4
#define N_DIM 256
#define D_MODEL 256
#define HEADS 8
#define DHEAD 32
#define INNER 256
#define QKV_COLS 768
#define M_TOTAL (S_DIM * B_DIM * N_DIM)   // 65536
#define SCALE 0.17677669529663687f
#define KS 512            // stored split width: [hi(256) | lo(256)]
#define NCHUNKS 12        // logical K' = 768 = 12 x 64

typedef unsigned long long ull;

// ---- mma / ldmatrix / cp.async helpers (baseline PTX, sm_80+) ----
__device__ __forceinline__ uint32_t smem_u32(const void* p) {
    uint32_t a;
    asm("{ .reg .u64 t; cvta.to.shared.u64 t, %1; cvt.u32.u64 %0, t; }"
        : "=r"(a) : "l"(p));
    return a;
}
__device__ __forceinline__ void ldm4(uint32_t* r, uint32_t addr) {
    asm volatile("ldmatrix.sync.aligned.m8n8.x4.shared.b16 {%0,%1,%2,%3}, [%4];"
        : "=r"(r[0]), "=r"(r[1]), "=r"(r[2]), "=r"(r[3]) : "r"(addr));
}
__device__ __forceinline__ void mma16816(float* c, const uint32_t* a,
                                         uint32_t b0, uint32_t b1) {
    asm volatile("mma.sync.aligned.m16n8k16.row.col.f32.bf16.bf16.f32 "
        "{%0,%1,%2,%3}, {%4,%5,%6,%7}, {%8,%9}, {%0,%1,%2,%3};"
        : "+f"(c[0]), "+f"(c[1]), "+f"(c[2]), "+f"(c[3])
        : "r"(a[0]), "r"(a[1]), "r"(a[2]), "r"(a[3]), "r"(b0), "r"(b1));
}
__device__ __forceinline__ void cp16(uint32_t s, const void* g) {
    asm volatile("cp.async.cg.shared.global [%0], [%1], 16;" :: "r"(s), "l"(g));
}
__device__ __forceinline__ void cp_commit() {
    asm volatile("cp.async.commit_group;" ::: "memory");
}
template <int N>
__device__ __forceinline__ void cp_wait() {
    asm volatile("cp.async.wait_group %0;" :: "n"(N) : "memory");
}
// pack two f32 into bf16x2: low half = lo, high half = hi
__device__ __forceinline__ uint32_t packbf(float lo, float hi) {
    uint32_t r;
    asm("cvt.rn.bf16x2.f32 %0, %1, %2;" : "=r"(r) : "f"(hi), "f"(lo));
    return r;
}
__device__ __forceinline__ float bf_lo(uint32_t u) { return __uint_as_float(u << 16); }
__device__ __forceinline__ float bf_hi(uint32_t u) { return __uint_as_float(u & 0xffff0000u); }

// Scratch (allocation-free rule: __device__ globals)
__device__ float g_qkv[(size_t)M_TOTAL * QKV_COLS];            // 192 MB
__device__ __nv_bfloat16 g_abf[(size_t)M_TOTAL * KS];          // 67 MB (split A)
__device__ __nv_bfloat16 g_wqt[(size_t)QKV_COLS * KS];         // W_qkv^T split
__device__ __nv_bfloat16 g_wot[(size_t)D_MODEL * KS];          // W_out^T split
__device__ unsigned g_maskpack[S_DIM][N_DIM][8];

// ---------------------------------------------------------------------------
// Prep kernels
// ---------------------------------------------------------------------------
__global__ void pack_mask_kernel(const int* __restrict__ mask) {
    const int s = blockIdx.x, i = threadIdx.x;
    const int* p = mask + ((size_t)s * N_DIM + i) * N_DIM;
    #pragma unroll
    for (int c = 0; c < 8; c++) {
        unsigned bits = 0;
        #pragma unroll 8
        for (int bb = 0; bb < 32; bb++)
            bits |= (unsigned)(p[c * 32 + bb] != 0) << bb;
        g_maskpack[s][i][c] = bits;
    }
}

__global__ void split_a_kernel(const float* __restrict__ src,
                               __nv_bfloat16* __restrict__ dst) {
    const size_t row = blockIdx.x;
    const int col = threadIdx.x;
    float x = src[row * 256 + col];
    __nv_bfloat16 hi = __float2bfloat16_rn(x);
    __nv_bfloat16 lo = __float2bfloat16_rn(x - __bfloat162float(hi));
    __nv_bfloat16* d = dst + row * KS;
    d[col] = hi; d[256 + col] = lo;
}

__global__ void split_w_kernel(const float* __restrict__ W,
                               __nv_bfloat16* __restrict__ Wt, int Ncols) {
    const int n = blockIdx.x;
    const int k = threadIdx.x;
    float w = W[(size_t)k * Ncols + n];
    __nv_bfloat16 hi = __float2bfloat16_rn(w);
    __nv_bfloat16 lo = __float2bfloat16_rn(w - __bfloat162float(hi));
    __nv_bfloat16* d = Wt + (size_t)n * KS;
    d[k] = hi; d[256 + k] = lo;
}

// ---------------------------------------------------------------------------
// Tensor-core GEMM (R9, verified): C = A' x B'^T, logical K' = 768.
// ---------------------------------------------------------------------------
#define GEMM_SMEM (64 * 1024)

__constant__ int c_cmapA[NCHUNKS] = {0,1,2,3,4,5,6,7,0,1,2,3};
__constant__ int c_cmapB[NCHUNKS] = {0,1,2,3,0,1,2,3,4,5,6,7};

__global__ __launch_bounds__(256, 2)
void gemm_mma_kernel(const __nv_bfloat16* __restrict__ A,
                     const __nv_bfloat16* __restrict__ Bt,
                     float* __restrict__ C, const float* __restrict__ bias,
                     int Ntot) {
    extern __shared__ __align__(1024) char smx[];
    const uint32_t sb = smem_u32(smx);
    const int tid = threadIdx.x;
    const int lane = tid & 31, w = tid >> 5;
    const int bx = blockIdx.x, by = blockIdx.y;
    const size_t arow0 = (size_t)by * 128;
    const size_t brow0 = (size_t)bx * 128;
    const int mrow = (w & 3) * 32;
    const int ncol = (w >> 2) * 64;

    uint32_t aoff[2], boff[4];
    const uint32_t khA = (lane >> 4) * 16;
    const uint32_t khB = ((lane >> 3) & 1) * 16;
    #pragma unroll
    for (int mt = 0; mt < 2; mt++) {
        uint32_t rp = (uint32_t)(mrow + mt * 16 + (lane & 15)) * 128;
        aoff[mt] = rp ^ ((rp >> 3) & 0x70);
    }
    #pragma unroll
    for (int nt = 0; nt < 4; nt++) {
        uint32_t n = ncol + nt * 16 + (lane & 7) + ((lane >> 4) << 3);
        uint32_t rp = n * 128;
        boff[nt] = rp ^ ((rp >> 3) & 0x70);
    }

    const char* Abase = (const char*)(A + arow0 * KS);
    const char* Bbase = (const char*)(Bt + brow0 * KS);
    const int crow = tid >> 1;
    const int cpart = (tid & 1) * 4;

    float acc[2][8][4];
    #pragma unroll
    for (int mt = 0; mt < 2; mt++)
        #pragma unroll
        for (int nt = 0; nt < 8; nt++)
            #pragma unroll
            for (int q = 0; q < 4; q++) acc[mt][nt][q] = 0.0f;

    auto issue = [&](int c, int buf) {
        const char* Ac = Abase + c_cmapA[c] * 128;
        const char* Bc = Bbase + c_cmapB[c] * 128;
        uint32_t sA = sb + buf * 16384;
        uint32_t sB = sb + 32768 + buf * 16384;
        #pragma unroll
        for (int p = 0; p < 4; p++) {
            uint32_t off = (uint32_t)crow * 128 + (cpart + p) * 16;
            uint32_t sw = off ^ ((off >> 3) & 0x70);
            cp16(sA + sw, Ac + (size_t)crow * (KS * 2) + (cpart + p) * 16);
            cp16(sB + sw, Bc + (size_t)crow * (KS * 2) + (cpart + p) * 16);
        }
        cp_commit();
    };

    issue(0, 0);
    for (int c = 0; c < NCHUNKS; c++) {
        const int buf = c & 1;
        if (c + 1 < NCHUNKS) {
            issue(c + 1, buf ^ 1);
            cp_wait<1>();
        } else {
            cp_wait<0>();
        }
        __syncthreads();

        const uint32_t sA = sb + buf * 16384;
        const uint32_t sB = sb + 32768 + buf * 16384;
        #pragma unroll
        for (int ks = 0; ks < 4; ks++) {
            uint32_t a[2][4], b[4][4];
            #pragma unroll
            for (int mt = 0; mt < 2; mt++)
                ldm4(a[mt], sA + (aoff[mt] ^ (ks * 32 + khA)));
            #pragma unroll
            for (int nt = 0; nt < 4; nt++)
                ldm4(b[nt], sB + (boff[nt] ^ (ks * 32 + khB)));
            #pragma unroll
            for (int mt = 0; mt < 2; mt++)
                #pragma unroll
                for (int nt = 0; nt < 4; nt++) {
                    mma16816(acc[mt][2 * nt + 0], a[mt], b[nt][0], b[nt][1]);
                    mma16816(acc[mt][2 * nt + 1], a[mt], b[nt][2], b[nt][3]);
                }
        }
        __syncthreads();
    }

    const int g = lane >> 2, t4 = lane & 3;
    #pragma unroll
    for (int mt = 0; mt < 2; mt++) {
        #pragma unroll
        for (int sub = 0; sub < 2; sub++) {
            size_t row = arow0 + mrow + mt * 16 + g + sub * 8;
            float* Cr = C + row * Ntot + brow0;
            #pragma unroll
            for (int nt = 0; nt < 8; nt++) {
                int col = ncol + nt * 8 + 2 * t4;
                float2 v = make_float2(acc[mt][nt][sub * 2 + 0],
                                       acc[mt][nt][sub * 2 + 1]);
                if (bias) {
                    v.x += __ldg(bias + brow0 + col);
                    v.y += __ldg(bias + brow0 + col + 1);
                }
                *(float2*)(Cr + col) = v;
            }
        }
    }
}

// ---------------------------------------------------------------------------
// MMA flash-attention: one CTA per (s,b,h), 256 threads (8 warps x 32 rows).
// smem: sQ[256][64] (hi|lo, 128B rows, SW128), sK same, sVt[64][256]
// (V transposed, hi rows 0-31 / lo rows 32-63, 512B rows, row-XOR swizzle),
// sM[256][8] mask words. No-max softmax; S and P·V on tensor pipe.
// ---------------------------------------------------------------------------
#define AQ_OFF 0
#define AK_OFF 32768
#define AV_OFF 65536
#define AM_OFF 98304
#define ATTN_SMEM_BYTES (98304 + 8192)

__global__ __launch_bounds__(256, 1)
void attn_mma_kernel(const float* __restrict__ qkv,
                     __nv_bfloat16* __restrict__ outsp) {
    extern __shared__ __align__(1024) char smx[];
    const uint32_t sb = smem_u32(smx);
    const int tid = threadIdx.x;
    const int lane = tid & 31, w = tid >> 5;
    const int g = lane >> 2, t4 = lane & 3;
    const int h = blockIdx.x, b = blockIdx.y, s = blockIdx.z;
    const size_t base = ((size_t)(s * B_DIM + b) * N_DIM) * QKV_COLS;

    // ---- load + split phase ----
    unsigned* sM = (unsigned*)(smx + AM_OFF);
    #pragma unroll
    for (int t = 0; t < 8; t++) {
        int idx = t * 256 + tid;          // 2048 = 256 rows x 8 f4-chunks
        int j = idx >> 3, d4 = (idx & 7) * 4;
        const float* rowp = qkv + base + (size_t)j * QKV_COLS + h * DHEAD;
        // Q (pre-scaled), K: hi|lo into 128B rows
        float4 qv = *(const float4*)(rowp + d4);
        float4 kv = *(const float4*)(rowp + INNER + d4);
        float qs[4] = {qv.x * SCALE, qv.y * SCALE, qv.z * SCALE, qv.w * SCALE};
        float kk[4] = {kv.x, kv.y, kv.z, kv.w};
        uint32_t qh[2], ql[2], kh[2], kl[2];
        #pragma unroll
        for (int p = 0; p < 2; p++) {
            float a0 = qs[2 * p], a1 = qs[2 * p + 1];
            uint32_t uh = packbf(a0, a1);
            qh[p] = uh;
            ql[p] = packbf(a0 - bf_lo(uh), a1 - bf_hi(uh));
            float b0 = kk[2 * p], b1 = kk[2 * p + 1];
            uint32_t vh = packbf(b0, b1);
            kh[p] = vh;
            kl[p] = packbf(b0 - bf_lo(vh), b1 - bf_hi(vh));
        }
        uint32_t offh = (uint32_t)j * 128 + d4 * 2;
        uint32_t offl = offh + 64;
        uint32_t swh = offh ^ ((offh >> 3) & 0x70);
        uint32_t swl = offl ^ ((offl >> 3) & 0x70);
        *(uint2*)(smx + AQ_OFF + swh) = make_uint2(qh[0], qh[1]);
        *(uint2*)(smx + AQ_OFF + swl) = make_uint2(ql[0], ql[1]);
        *(uint2*)(smx + AK_OFF + swh) = make_uint2(kh[0], kh[1]);
        *(uint2*)(smx + AK_OFF + swl) = make_uint2(kl[0], kl[1]);
        // V transposed: Vt[d][j] (hi), Vt[d+32][j] (lo); 512B rows
        float4 vv = *(const float4*)(rowp + 2 * INNER + d4);
        float ve[4] = {vv.x, vv.y, vv.z, vv.w};
        #pragma unroll
        for (int e = 0; e < 4; e++) {
            int d = d4 + e;
            __nv_bfloat16 hi = __float2bfloat16_rn(ve[e]);
            __nv_bfloat16 lo = __float2bfloat16_rn(ve[e] - __bfloat162float(hi));
            uint32_t oh = (uint32_t)d * 512 + j * 2;
            uint32_t ol = (uint32_t)(d + 32) * 512 + j * 2;
            *(__nv_bfloat16*)(smx + AV_OFF + (oh ^ (((oh >> 9) & 7) << 4))) = hi;
            *(__nv_bfloat16*)(smx + AV_OFF + (ol ^ (((ol >> 9) & 7) << 4))) = lo;
        }
        // mask words
        sM[idx] = g_maskpack[s][idx >> 3][idx & 7];
    }
    __syncthreads();

    // ---- per-warp fragment offsets ----
    const uint32_t khA = (lane >> 4) * 16;
    const uint32_t khB = ((lane >> 3) & 1) * 16;
    uint32_t qroff[2];
    #pragma unroll
    for (int mt = 0; mt < 2; mt++) {
        uint32_t rp = (uint32_t)(w * 32 + mt * 16 + (lane & 15)) * 128;
        qroff[mt] = rp ^ ((rp >> 3) & 0x70);
    }
    // Q frags hoisted: [mt][kt] (kt 0,1 = hi d0-15,16-31 ; 2,3 = lo)
    uint32_t qf[2][4][4];
    #pragma unroll
    for (int mt = 0; mt < 2; mt++)
        #pragma unroll
        for (int kt = 0; kt < 4; kt++)
            ldm4(qf[mt][kt], sb + AQ_OFF + (qroff[mt] ^ (kt * 32 + khA)));
    // V frag row offsets (n = d rows of Vt)
    uint32_t vroffh[2], vroffl[2];
    #pragma unroll
    for (int dn = 0; dn < 2; dn++) {
        uint32_t nh = dn * 16 + (lane & 7) + ((lane >> 4) << 3);
        uint32_t rph = nh * 512;
        vroffh[dn] = rph ^ (((rph >> 9) & 7) << 4);
        uint32_t rpl = (nh + 32) * 512;
        vroffl[dn] = rpl ^ (((rpl >> 9) & 7) << 4);
    }

    float oacc[2][4][4];
    #pragma unroll
    for (int mt = 0; mt < 2; mt++)
        #pragma unroll
        for (int nt = 0; nt < 4; nt++)
            #pragma unroll
            for (int q = 0; q < 4; q++) oacc[mt][nt][q] = 0.0f;
    float lsum[2][2] = {{0.0f, 0.0f}, {0.0f, 0.0f}};

    // QK k-pairs: (ktA, ktB): hi*hi, lo*hi, hi*lo
    const int KPA[6] = {0, 1, 2, 3, 0, 1};
    const int KPB[6] = {0, 1, 0, 1, 2, 3};

    for (int jt = 0; jt < 4; jt++) {
        const int j0 = jt * 64;
        float sfrag[2][8][4];
        #pragma unroll
        for (int mt = 0; mt < 2; mt++)
            #pragma unroll
            for (int nt = 0; nt < 8; nt++)
                #pragma unroll
                for (int q = 0; q < 4; q++) sfrag[mt][nt][q] = 0.0f;

        // ---- S = Q K^T ----
        #pragma unroll
        for (int nt = 0; nt < 4; nt++) {
            uint32_t n = (uint32_t)(j0 + nt * 16 + (lane & 7) + ((lane >> 4) << 3));
            uint32_t rp = n * 128;
            uint32_t kro = rp ^ ((rp >> 3) & 0x70);
            uint32_t kb[4][4];
            #pragma unroll
            for (int kt = 0; kt < 4; kt++)
                ldm4(kb[kt], sb + AK_OFF + (kro ^ (kt * 32 + khB)));
            #pragma unroll
            for (int pp = 0; pp < 6; pp++) {
                #pragma unroll
                for (int mt = 0; mt < 2; mt++) {
                    mma16816(sfrag[mt][2 * nt + 0], qf[mt][KPA[pp]],
                             kb[KPB[pp]][0], kb[KPB[pp]][1]);
                    mma16816(sfrag[mt][2 * nt + 1], qf[mt][KPA[pp]],
                             kb[KPB[pp]][2], kb[KPB[pp]][3]);
                }
            }
        }

        // ---- mask + exp + rowsum ----
        #pragma unroll
        for (int mt = 0; mt < 2; mt++) {
            int i0 = w * 32 + mt * 16 + g;
            unsigned mwA0 = sM[i0 * 8 + 2 * jt], mwA1 = sM[i0 * 8 + 2 * jt + 1];
            unsigned mwB0 = sM[(i0 + 8) * 8 + 2 * jt], mwB1 = sM[(i0 + 8) * 8 + 2 * jt + 1];
            #pragma unroll
            for (int nt = 0; nt < 8; nt++) {
                unsigned mA = (nt < 4) ? mwA0 : mwA1;
                unsigned mB = (nt < 4) ? mwB0 : mwB1;
                int bb = (nt & 3) * 8 + 2 * t4;
                float* c = sfrag[mt][nt];
                float p0 = ((mA >> bb) & 1u) ? __expf(c[0]) : 0.0f;
                float p1 = ((mA >> (bb + 1)) & 1u) ? __expf(c[1]) : 0.0f;
                float p2 = ((mB >> bb) & 1u) ? __expf(c[2]) : 0.0f;
                float p3 = ((mB >> (bb + 1)) & 1u) ? __expf(c[3]) : 0.0f;
                c[0] = p0; c[1] = p1; c[2] = p2; c[3] = p3;
                lsum[mt][0] += p0 + p1;
                lsum[mt][1] += p2 + p3;
            }
        }

        // ---- P V: 3 terms (Phi*Vhi + Plo*Vhi + Phi*Vlo) ----
        #pragma unroll
        for (int jkt = 0; jkt < 4; jkt++) {
            uint32_t koff = (uint32_t)(j0 * 2 + jkt * 32) + khB;
            uint32_t vbh[2][4], vbl[2][4];
            #pragma unroll
            for (int dn = 0; dn < 2; dn++) {
                ldm4(vbh[dn], sb + AV_OFF + (vroffh[dn] ^ koff));
                ldm4(vbl[dn], sb + AV_OFF + (vroffl[dn] ^ koff));
            }
            #pragma unroll
            for (int mt = 0; mt < 2; mt++) {
                float* cA = sfrag[mt][2 * jkt + 0];
                float* cB = sfrag[mt][2 * jkt + 1];
                uint32_t ahi[4], alo[4];
                ahi[0] = packbf(cA[0], cA[1]);
                ahi[1] = packbf(cA[2], cA[3]);
                ahi[2] = packbf(cB[0], cB[1]);
                ahi[3] = packbf(cB[2], cB[3]);
                alo[0] = packbf(cA[0] - bf_lo(ahi[0]), cA[1] - bf_hi(ahi[0]));
                alo[1] = packbf(cA[2] - bf_lo(ahi[1]), cA[3] - bf_hi(ahi[1]));
                alo[2] = packbf(cB[0] - bf_lo(ahi[2]), cB[1] - bf_hi(ahi[2]));
                alo[3] = packbf(cB[2] - bf_lo(ahi[3]), cB[3] - bf_hi(ahi[3]));
                #pragma unroll
                for (int dn = 0; dn < 2; dn++) {
                    mma16816(oacc[mt][2 * dn + 0], ahi, vbh[dn][0], vbh[dn][1]);
                    mma16816(oacc[mt][2 * dn + 1], ahi, vbh[dn][2], vbh[dn][3]);
                    mma16816(oacc[mt][2 * dn + 0], alo, vbh[dn][0], vbh[dn][1]);
                    mma16816(oacc[mt][2 * dn + 1], alo, vbh[dn][2], vbh[dn][3]);
                    mma16816(oacc[mt][2 * dn + 0], ahi, vbl[dn][0], vbl[dn][1]);
                    mma16816(oacc[mt][2 * dn + 1], ahi, vbl[dn][2], vbl[dn][3]);
                }
            }
        }
    }

    // ---- normalize + split + store ----
    const size_t rbase = (size_t)(s * B_DIM + b) * N_DIM;
    #pragma unroll
    for (int mt = 0; mt < 2; mt++) {
        #pragma unroll
        for (int h2 = 0; h2 < 2; h2++) {
            float l = lsum[mt][h2];
            l += __shfl_xor_sync(0xffffffffu, l, 1);
            l += __shfl_xor_sync(0xffffffffu, l, 2);
            float inv = 1.0f / l;
            int i = w * 32 + mt * 16 + g + 8 * h2;
            __nv_bfloat16* o = outsp + (rbase + i) * KS + h * DHEAD;
            #pragma unroll
            for (int nt = 0; nt < 4; nt++) {
                int d = nt * 8 + 2 * t4;
                float v0 = oacc[mt][nt][2 * h2 + 0] * inv;
                float v1 = oacc[mt][nt][2 * h2 + 1] * inv;
                uint32_t uh = packbf(v0, v1);
                uint32_t ul = packbf(v0 - bf_lo(uh), v1 - bf_hi(uh));
                *(uint32_t*)(o + d) = uh;
                *(uint32_t*)(o + 256 + d) = ul;
            }
        }
    }
}

// ---------------------------------------------------------------------------
// Launch
// ---------------------------------------------------------------------------
extern "C" void kernel_launch(void* const* d_in, const int* in_sizes, int n_in,
                              void* d_out, int out_size) {
    const float* x    = (const float*)d_in[0];
    const int*   mask = (const int*)d_in[1];
    const float* Wqkv = (const float*)d_in[2];
    const float* Wout = (const float*)d_in[3];
    const float* bout = (const float*)d_in[4];
    float* out = (float*)d_out;

    float* qkvbuf = nullptr;
    __nv_bfloat16 *abf = nullptr, *wqt = nullptr, *wot = nullptr;
    cudaGetSymbolAddress((void**)&qkvbuf, g_qkv);
    cudaGetSymbolAddress((void**)&abf, g_abf);
    cudaGetSymbolAddress((void**)&wqt, g_wqt);
    cudaGetSymbolAddress((void**)&wot, g_wot);

    cudaFuncSetAttribute(attn_mma_kernel, cudaFuncAttributeMaxDynamicSharedMemorySize,
                         ATTN_SMEM_BYTES);
    cudaFuncSetAttribute(gemm_mma_kernel, cudaFuncAttributeMaxDynamicSharedMemorySize,
                         GEMM_SMEM);

    // Prep
    pack_mask_kernel<<<S_DIM, N_DIM>>>(mask);
    split_w_kernel<<<QKV_COLS, 256>>>(Wqkv, wqt, QKV_COLS);
    split_w_kernel<<<D_MODEL, 256>>>(Wout, wot, D_MODEL);
    split_a_kernel<<<M_TOTAL, 256>>>(x, abf);

    // 1) QKV projection (tensor cores)
    {
        dim3 grid(QKV_COLS / 128, M_TOTAL / 128);
        gemm_mma_kernel<<<grid, 256, GEMM_SMEM>>>(abf, wqt, qkvbuf, nullptr,
                                                  QKV_COLS);
    }
    // 2) Attention (tensor cores; writes split bf16 output directly)
    {
        dim3 grid(HEADS, B_DIM, S_DIM);
        attn_mma_kernel<<<grid, 256, ATTN_SMEM_BYTES>>>(qkvbuf, abf);
    }
    // 3) Output projection (reads fused-split attn output)
    {
        dim3 grid(D_MODEL / 128, M_TOTAL / 128);
        gemm_mma_kernel<<<grid, 256, GEMM_SMEM>>>(abf, wot, out, bout,
                                                  D_MODEL);
    }
}

// round 13
// speedup vs baseline: 2.1400x; 1.0344x over previous
#include <cuda_runtime.h>
#include <cuda_bf16.h>
#include <cstdint>
#include <cstddef>

// Problem constants
#define S_DIM 64
#define B_DIM 4
#define N_DIM 256
#define D_MODEL 256
#define HEADS 8
#define DHEAD 32
#define INNER 256
#define QKV_COLS 768
#define M_TOTAL (S_DIM * B_DIM * N_DIM)   // 65536
#define SCALE 0.17677669529663687f
#define KS 512            // stored split width: [hi(256) | lo(256)]
#define NCHUNKS 12        // logical K' = 768 = 12 x 64

typedef unsigned long long ull;

// ---- mma / ldmatrix / cp.async helpers (baseline PTX, sm_80+) ----
__device__ __forceinline__ uint32_t smem_u32(const void* p) {
    uint32_t a;
    asm("{ .reg .u64 t; cvta.to.shared.u64 t, %1; cvt.u32.u64 %0, t; }"
        : "=r"(a) : "l"(p));
    return a;
}
__device__ __forceinline__ void ldm4(uint32_t* r, uint32_t addr) {
    asm volatile("ldmatrix.sync.aligned.m8n8.x4.shared.b16 {%0,%1,%2,%3}, [%4];"
        : "=r"(r[0]), "=r"(r[1]), "=r"(r[2]), "=r"(r[3]) : "r"(addr));
}
__device__ __forceinline__ void mma16816(float* c, const uint32_t* a,
                                         uint32_t b0, uint32_t b1) {
    asm volatile("mma.sync.aligned.m16n8k16.row.col.f32.bf16.bf16.f32 "
        "{%0,%1,%2,%3}, {%4,%5,%6,%7}, {%8,%9}, {%0,%1,%2,%3};"
        : "+f"(c[0]), "+f"(c[1]), "+f"(c[2]), "+f"(c[3])
        : "r"(a[0]), "r"(a[1]), "r"(a[2]), "r"(a[3]), "r"(b0), "r"(b1));
}
__device__ __forceinline__ void cp16(uint32_t s, const void* g) {
    asm volatile("cp.async.cg.shared.global [%0], [%1], 16;" :: "r"(s), "l"(g));
}
__device__ __forceinline__ void cp_commit() {
    asm volatile("cp.async.commit_group;" ::: "memory");
}
template <int N>
__device__ __forceinline__ void cp_wait() {
    asm volatile("cp.async.wait_group %0;" :: "n"(N) : "memory");
}
// pack two f32 into bf16x2: low half = lo arg, high half = hi arg
__device__ __forceinline__ uint32_t packbf(float lo, float hi) {
    uint32_t r;
    asm("cvt.rn.bf16x2.f32 %0, %1, %2;" : "=r"(r) : "f"(hi), "f"(lo));
    return r;
}
__device__ __forceinline__ float bf_lo(uint32_t u) { return __uint_as_float(u << 16); }
__device__ __forceinline__ float bf_hi(uint32_t u) { return __uint_as_float(u & 0xffff0000u); }

// Scratch (allocation-free rule: __device__ globals)
__device__ float g_qkv[(size_t)M_TOTAL * QKV_COLS];            // 192 MB
__device__ __nv_bfloat16 g_abf[(size_t)M_TOTAL * KS];          // 67 MB (split A)
__device__ __nv_bfloat16 g_wqt[(size_t)QKV_COLS * KS];         // W_qkv^T split
__device__ __nv_bfloat16 g_wot[(size_t)D_MODEL * KS];          // W_out^T split
__device__ unsigned g_maskpack[S_DIM][N_DIM][8];

// ---------------------------------------------------------------------------
// Prep kernels
// ---------------------------------------------------------------------------
__global__ void pack_mask_kernel(const int* __restrict__ mask) {
    const int s = blockIdx.x, i = threadIdx.x;
    const int* p = mask + ((size_t)s * N_DIM + i) * N_DIM;
    #pragma unroll
    for (int c = 0; c < 8; c++) {
        unsigned bits = 0;
        #pragma unroll 8
        for (int bb = 0; bb < 32; bb++)
            bits |= (unsigned)(p[c * 32 + bb] != 0) << bb;
        g_maskpack[s][i][c] = bits;
    }
}

// split fp32 [rows,256] -> bf16 [rows, hi256|lo256], grid-stride float4
__global__ __launch_bounds__(256)
void split_a_kernel(const float* __restrict__ src,
                    __nv_bfloat16* __restrict__ dst) {
    const int nf4 = M_TOTAL * 64;   // total float4s
    for (int idx = blockIdx.x * blockDim.x + threadIdx.x; idx < nf4;
         idx += gridDim.x * blockDim.x) {
        int row = idx >> 6;
        int c4 = (idx & 63) * 4;
        float4 v = *(const float4*)(src + (size_t)row * 256 + c4);
        uint32_t h0 = packbf(v.x, v.y);
        uint32_t h1 = packbf(v.z, v.w);
        uint32_t l0 = packbf(v.x - bf_lo(h0), v.y - bf_hi(h0));
        uint32_t l1 = packbf(v.z - bf_lo(h1), v.w - bf_hi(h1));
        __nv_bfloat16* d = dst + (size_t)row * KS;
        *(uint2*)(d + c4) = make_uint2(h0, h1);
        *(uint2*)(d + 256 + c4) = make_uint2(l0, l1);
    }
}

// W [256 (k), Ncols] fp32 -> Wt bf16 [Ncols (n)][hi256|lo256].
// For the QKV weight (Ncols==768), q columns (n<256) are pre-scaled by SCALE.
__global__ void split_w_kernel(const float* __restrict__ W,
                               __nv_bfloat16* __restrict__ Wt, int Ncols) {
    const int n = blockIdx.x;
    const int k = threadIdx.x;
    float w = W[(size_t)k * Ncols + n];
    if (Ncols == QKV_COLS && n < 256) w *= SCALE;
    __nv_bfloat16 hi = __float2bfloat16_rn(w);
    __nv_bfloat16 lo = __float2bfloat16_rn(w - __bfloat162float(hi));
    __nv_bfloat16* d = Wt + (size_t)n * KS;
    d[k] = hi; d[256 + k] = lo;
}

// ---------------------------------------------------------------------------
// Tensor-core GEMM: C = A' x B'^T, logical K' = 768, 3-stage cp.async pipe.
// ---------------------------------------------------------------------------
#define GEMM_SMEM (96 * 1024)   // 3 x (A 16K + B 16K)

__constant__ int c_cmapA[NCHUNKS] = {0,1,2,3,4,5,6,7,0,1,2,3};
__constant__ int c_cmapB[NCHUNKS] = {0,1,2,3,0,1,2,3,4,5,6,7};

__global__ __launch_bounds__(256, 2)
void gemm_mma_kernel(const __nv_bfloat16* __restrict__ A,
                     const __nv_bfloat16* __restrict__ Bt,
                     float* __restrict__ C, const float* __restrict__ bias,
                     int Ntot) {
    extern __shared__ __align__(1024) char smx[];
    const uint32_t sb = smem_u32(smx);
    const int tid = threadIdx.x;
    const int lane = tid & 31, w = tid >> 5;
    const int bx = blockIdx.x, by = blockIdx.y;
    const size_t arow0 = (size_t)by * 128;
    const size_t brow0 = (size_t)bx * 128;
    const int mrow = (w & 3) * 32;
    const int ncol = (w >> 2) * 64;

    uint32_t aoff[2], boff[4];
    const uint32_t khA = (lane >> 4) * 16;
    const uint32_t khB = ((lane >> 3) & 1) * 16;
    #pragma unroll
    for (int mt = 0; mt < 2; mt++) {
        uint32_t rp = (uint32_t)(mrow + mt * 16 + (lane & 15)) * 128;
        aoff[mt] = rp ^ ((rp >> 3) & 0x70);
    }
    #pragma unroll
    for (int nt = 0; nt < 4; nt++) {
        uint32_t n = ncol + nt * 16 + (lane & 7) + ((lane >> 4) << 3);
        uint32_t rp = n * 128;
        boff[nt] = rp ^ ((rp >> 3) & 0x70);
    }

    const char* Abase = (const char*)(A + arow0 * KS);
    const char* Bbase = (const char*)(Bt + brow0 * KS);
    const int crow = tid >> 1;
    const int cpart = (tid & 1) * 4;

    float acc[2][8][4];
    #pragma unroll
    for (int mt = 0; mt < 2; mt++)
        #pragma unroll
        for (int nt = 0; nt < 8; nt++)
            #pragma unroll
            for (int q = 0; q < 4; q++) acc[mt][nt][q] = 0.0f;

    auto issue = [&](int c, int buf) {
        const char* Ac = Abase + c_cmapA[c] * 128;
        const char* Bc = Bbase + c_cmapB[c] * 128;
        uint32_t sA = sb + buf * 16384;
        uint32_t sB = sb + 49152 + buf * 16384;
        #pragma unroll
        for (int p = 0; p < 4; p++) {
            uint32_t off = (uint32_t)crow * 128 + (cpart + p) * 16;
            uint32_t sw = off ^ ((off >> 3) & 0x70);
            cp16(sA + sw, Ac + (size_t)crow * (KS * 2) + (cpart + p) * 16);
            cp16(sB + sw, Bc + (size_t)crow * (KS * 2) + (cpart + p) * 16);
        }
        cp_commit();
    };

    issue(0, 0);
    issue(1, 1);
    for (int c = 0; c < NCHUNKS; c++) {
        const int buf = c % 3;
        if (c + 2 < NCHUNKS) {
            issue(c + 2, (c + 2) % 3);
            cp_wait<2>();
        } else if (c + 1 < NCHUNKS) {
            cp_wait<1>();
        } else {
            cp_wait<0>();
        }
        __syncthreads();

        const uint32_t sA = sb + buf * 16384;
        const uint32_t sB = sb + 49152 + buf * 16384;
        #pragma unroll
        for (int ks = 0; ks < 4; ks++) {
            uint32_t a[2][4], b[4][4];
            #pragma unroll
            for (int mt = 0; mt < 2; mt++)
                ldm4(a[mt], sA + (aoff[mt] ^ (ks * 32 + khA)));
            #pragma unroll
            for (int nt = 0; nt < 4; nt++)
                ldm4(b[nt], sB + (boff[nt] ^ (ks * 32 + khB)));
            #pragma unroll
            for (int mt = 0; mt < 2; mt++)
                #pragma unroll
                for (int nt = 0; nt < 4; nt++) {
                    mma16816(acc[mt][2 * nt + 0], a[mt], b[nt][0], b[nt][1]);
                    mma16816(acc[mt][2 * nt + 1], a[mt], b[nt][2], b[nt][3]);
                }
        }
        __syncthreads();
    }

    const int g = lane >> 2, t4 = lane & 3;
    #pragma unroll
    for (int mt = 0; mt < 2; mt++) {
        #pragma unroll
        for (int sub = 0; sub < 2; sub++) {
            size_t row = arow0 + mrow + mt * 16 + g + sub * 8;
            float* Cr = C + row * Ntot + brow0;
            #pragma unroll
            for (int nt = 0; nt < 8; nt++) {
                int col = ncol + nt * 8 + 2 * t4;
                float2 v = make_float2(acc[mt][nt][sub * 2 + 0],
                                       acc[mt][nt][sub * 2 + 1]);
                if (bias) {
                    v.x += __ldg(bias + brow0 + col);
                    v.y += __ldg(bias + brow0 + col + 1);
                }
                *(float2*)(Cr + col) = v;
            }
        }
    }
}

// ---------------------------------------------------------------------------
// MMA flash-attention (R11, verified): one CTA per (s,b,h), 8 warps.
// q arrives pre-scaled (SCALE folded into W_qkv q-columns).
// ---------------------------------------------------------------------------
#define AQ_OFF 0
#define AK_OFF 32768
#define AV_OFF 65536
#define AM_OFF 98304
#define ATTN_SMEM_BYTES (98304 + 8192)

__global__ __launch_bounds__(256, 1)
void attn_mma_kernel(const float* __restrict__ qkv,
                     __nv_bfloat16* __restrict__ outsp) {
    extern __shared__ __align__(1024) char smx[];
    const uint32_t sb = smem_u32(smx);
    const int tid = threadIdx.x;
    const int lane = tid & 31, w = tid >> 5;
    const int g = lane >> 2, t4 = lane & 3;
    const int h = blockIdx.x, b = blockIdx.y, s = blockIdx.z;
    const size_t base = ((size_t)(s * B_DIM + b) * N_DIM) * QKV_COLS;

    // ---- load + split phase ----
    unsigned* sM = (unsigned*)(smx + AM_OFF);
    #pragma unroll
    for (int t = 0; t < 8; t++) {
        int idx = t * 256 + tid;
        int j = idx >> 3, d4 = (idx & 7) * 4;
        const float* rowp = qkv + base + (size_t)j * QKV_COLS + h * DHEAD;
        float4 qv = *(const float4*)(rowp + d4);
        float4 kv = *(const float4*)(rowp + INNER + d4);
        float qs[4] = {qv.x, qv.y, qv.z, qv.w};
        float kk[4] = {kv.x, kv.y, kv.z, kv.w};
        uint32_t qh[2], ql[2], kh[2], kl[2];
        #pragma unroll
        for (int p = 0; p < 2; p++) {
            float a0 = qs[2 * p], a1 = qs[2 * p + 1];
            uint32_t uh = packbf(a0, a1);
            qh[p] = uh;
            ql[p] = packbf(a0 - bf_lo(uh), a1 - bf_hi(uh));
            float b0 = kk[2 * p], b1 = kk[2 * p + 1];
            uint32_t vh = packbf(b0, b1);
            kh[p] = vh;
            kl[p] = packbf(b0 - bf_lo(vh), b1 - bf_hi(vh));
        }
        uint32_t offh = (uint32_t)j * 128 + d4 * 2;
        uint32_t offl = offh + 64;
        uint32_t swh = offh ^ ((offh >> 3) & 0x70);
        uint32_t swl = offl ^ ((offl >> 3) & 0x70);
        *(uint2*)(smx + AQ_OFF + swh) = make_uint2(qh[0], qh[1]);
        *(uint2*)(smx + AQ_OFF + swl) = make_uint2(ql[0], ql[1]);
        *(uint2*)(smx + AK_OFF + swh) = make_uint2(kh[0], kh[1]);
        *(uint2*)(smx + AK_OFF + swl) = make_uint2(kl[0], kl[1]);
        float4 vv = *(const float4*)(rowp + 2 * INNER + d4);
        float ve[4] = {vv.x, vv.y, vv.z, vv.w};
        #pragma unroll
        for (int e = 0; e < 4; e++) {
            int d = d4 + e;
            __nv_bfloat16 hi = __float2bfloat16_rn(ve[e]);
            __nv_bfloat16 lo = __float2bfloat16_rn(ve[e] - __bfloat162float(hi));
            uint32_t oh = (uint32_t)d * 512 + j * 2;
            uint32_t ol = (uint32_t)(d + 32) * 512 + j * 2;
            *(__nv_bfloat16*)(smx + AV_OFF + (oh ^ (((oh >> 9) & 7) << 4))) = hi;
            *(__nv_bfloat16*)(smx + AV_OFF + (ol ^ (((ol >> 9) & 7) << 4))) = lo;
        }
        sM[idx] = g_maskpack[s][idx >> 3][idx & 7];
    }
    __syncthreads();

    const uint32_t khA = (lane >> 4) * 16;
    const uint32_t khB = ((lane >> 3) & 1) * 16;
    uint32_t qroff[2];
    #pragma unroll
    for (int mt = 0; mt < 2; mt++) {
        uint32_t rp = (uint32_t)(w * 32 + mt * 16 + (lane & 15)) * 128;
        qroff[mt] = rp ^ ((rp >> 3) & 0x70);
    }
    uint32_t qf[2][4][4];
    #pragma unroll
    for (int mt = 0; mt < 2; mt++)
        #pragma unroll
        for (int kt = 0; kt < 4; kt++)
            ldm4(qf[mt][kt], sb + AQ_OFF + (qroff[mt] ^ (kt * 32 + khA)));
    uint32_t vroffh[2], vroffl[2];
    #pragma unroll
    for (int dn = 0; dn < 2; dn++) {
        uint32_t nh = dn * 16 + (lane & 7) + ((lane >> 4) << 3);
        uint32_t rph = nh * 512;
        vroffh[dn] = rph ^ (((rph >> 9) & 7) << 4);
        uint32_t rpl = (nh + 32) * 512;
        vroffl[dn] = rpl ^ (((rpl >> 9) & 7) << 4);
    }

    float oacc[2][4][4];
    #pragma unroll
    for (int mt = 0; mt < 2; mt++)
        #pragma unroll
        for (int nt = 0; nt < 4; nt++)
            #pragma unroll
            for (int q = 0; q < 4; q++) oacc[mt][nt][q] = 0.0f;
    float lsum[2][2] = {{0.0f, 0.0f}, {0.0f, 0.0f}};

    const int KPA[6] = {0, 1, 2, 3, 0, 1};
    const int KPB[6] = {0, 1, 0, 1, 2, 3};

    for (int jt = 0; jt < 4; jt++) {
        const int j0 = jt * 64;
        float sfrag[2][8][4];
        #pragma unroll
        for (int mt = 0; mt < 2; mt++)
            #pragma unroll
            for (int nt = 0; nt < 8; nt++)
                #pragma unroll
                for (int q = 0; q < 4; q++) sfrag[mt][nt][q] = 0.0f;

        #pragma unroll
        for (int nt = 0; nt < 4; nt++) {
            uint32_t n = (uint32_t)(j0 + nt * 16 + (lane & 7) + ((lane >> 4) << 3));
            uint32_t rp = n * 128;
            uint32_t kro = rp ^ ((rp >> 3) & 0x70);
            uint32_t kb[4][4];
            #pragma unroll
            for (int kt = 0; kt < 4; kt++)
                ldm4(kb[kt], sb + AK_OFF + (kro ^ (kt * 32 + khB)));
            #pragma unroll
            for (int pp = 0; pp < 6; pp++) {
                #pragma unroll
                for (int mt = 0; mt < 2; mt++) {
                    mma16816(sfrag[mt][2 * nt + 0], qf[mt][KPA[pp]],
                             kb[KPB[pp]][0], kb[KPB[pp]][1]);
                    mma16816(sfrag[mt][2 * nt + 1], qf[mt][KPA[pp]],
                             kb[KPB[pp]][2], kb[KPB[pp]][3]);
                }
            }
        }

        #pragma unroll
        for (int mt = 0; mt < 2; mt++) {
            int i0 = w * 32 + mt * 16 + g;
            unsigned mwA0 = sM[i0 * 8 + 2 * jt], mwA1 = sM[i0 * 8 + 2 * jt + 1];
            unsigned mwB0 = sM[(i0 + 8) * 8 + 2 * jt], mwB1 = sM[(i0 + 8) * 8 + 2 * jt + 1];
            #pragma unroll
            for (int nt = 0; nt < 8; nt++) {
                unsigned mA = (nt < 4) ? mwA0 : mwA1;
                unsigned mB = (nt < 4) ? mwB0 : mwB1;
                int bb = (nt & 3) * 8 + 2 * t4;
                float* c = sfrag[mt][nt];
                float p0 = ((mA >> bb) & 1u) ? __expf(c[0]) : 0.0f;
                float p1 = ((mA >> (bb + 1)) & 1u) ? __expf(c[1]) : 0.0f;
                float p2 = ((mB >> bb) & 1u) ? __expf(c[2]) : 0.0f;
                float p3 = ((mB >> (bb + 1)) & 1u) ? __expf(c[3]) : 0.0f;
                c[0] = p0; c[1] = p1; c[2] = p2; c[3] = p3;
                lsum[mt][0] += p0 + p1;
                lsum[mt][1] += p2 + p3;
            }
        }

        #pragma unroll
        for (int jkt = 0; jkt < 4; jkt++) {
            uint32_t koff = (uint32_t)(j0 * 2 + jkt * 32) + khB;
            uint32_t vbh[2][4], vbl[2][4];
            #pragma unroll
            for (int dn = 0; dn < 2; dn++) {
                ldm4(vbh[dn], sb + AV_OFF + (vroffh[dn] ^ koff));
                ldm4(vbl[dn], sb + AV_OFF + (vroffl[dn] ^ koff));
            }
            #pragma unroll
            for (int mt = 0; mt < 2; mt++) {
                float* cA = sfrag[mt][2 * jkt + 0];
                float* cB = sfrag[mt][2 * jkt + 1];
                uint32_t ahi[4], alo[4];
                ahi[0] = packbf(cA[0], cA[1]);
                ahi[1] = packbf(cA[2], cA[3]);
                ahi[2] = packbf(cB[0], cB[1]);
                ahi[3] = packbf(cB[2], cB[3]);
                alo[0] = packbf(cA[0] - bf_lo(ahi[0]), cA[1] - bf_hi(ahi[0]));
                alo[1] = packbf(cA[2] - bf_lo(ahi[1]), cA[3] - bf_hi(ahi[1]));
                alo[2] = packbf(cB[0] - bf_lo(ahi[2]), cB[1] - bf_hi(ahi[2]));
                alo[3] = packbf(cB[2] - bf_lo(ahi[3]), cB[3] - bf_hi(ahi[3]));
                #pragma unroll
                for (int dn = 0; dn < 2; dn++) {
                    mma16816(oacc[mt][2 * dn + 0], ahi, vbh[dn][0], vbh[dn][1]);
                    mma16816(oacc[mt][2 * dn + 1], ahi, vbh[dn][2], vbh[dn][3]);
                    mma16816(oacc[mt][2 * dn + 0], alo, vbh[dn][0], vbh[dn][1]);
                    mma16816(oacc[mt][2 * dn + 1], alo, vbh[dn][2], vbh[dn][3]);
                    mma16816(oacc[mt][2 * dn + 0], ahi, vbl[dn][0], vbl[dn][1]);
                    mma16816(oacc[mt][2 * dn + 1], ahi, vbl[dn][2], vbl[dn][3]);
                }
            }
        }
    }

    const size_t rbase = (size_t)(s * B_DIM + b) * N_DIM;
    #pragma unroll
    for (int mt = 0; mt < 2; mt++) {
        #pragma unroll
        for (int h2 = 0; h2 < 2; h2++) {
            float l = lsum[mt][h2];
            l += __shfl_xor_sync(0xffffffffu, l, 1);
            l += __shfl_xor_sync(0xffffffffu, l, 2);
            float inv = 1.0f / l;
            int i = w * 32 + mt * 16 + g + 8 * h2;
            __nv_bfloat16* o = outsp + (rbase + i) * KS + h * DHEAD;
            #pragma unroll
            for (int nt = 0; nt < 4; nt++) {
                int d = nt * 8 + 2 * t4;
                float v0 = oacc[mt][nt][2 * h2 + 0] * inv;
                float v1 = oacc[mt][nt][2 * h2 + 1] * inv;
                uint32_t uh = packbf(v0, v1);
                uint32_t ul = packbf(v0 - bf_lo(uh), v1 - bf_hi(uh));
                *(uint32_t*)(o + d) = uh;
                *(uint32_t*)(o + 256 + d) = ul;
            }
        }
    }
}

// ---------------------------------------------------------------------------
// Launch
// ---------------------------------------------------------------------------
extern "C" void kernel_launch(void* const* d_in, const int* in_sizes, int n_in,
                              void* d_out, int out_size) {
    const float* x    = (const float*)d_in[0];
    const int*   mask = (const int*)d_in[1];
    const float* Wqkv = (const float*)d_in[2];
    const float* Wout = (const float*)d_in[3];
    const float* bout = (const float*)d_in[4];
    float* out = (float*)d_out;

    float* qkvbuf = nullptr;
    __nv_bfloat16 *abf = nullptr, *wqt = nullptr, *wot = nullptr;
    cudaGetSymbolAddress((void**)&qkvbuf, g_qkv);
    cudaGetSymbolAddress((void**)&abf, g_abf);
    cudaGetSymbolAddress((void**)&wqt, g_wqt);
    cudaGetSymbolAddress((void**)&wot, g_wot);

    cudaFuncSetAttribute(attn_mma_kernel, cudaFuncAttributeMaxDynamicSharedMemorySize,
                         ATTN_SMEM_BYTES);
    cudaFuncSetAttribute(gemm_mma_kernel, cudaFuncAttributeMaxDynamicSharedMemorySize,
                         GEMM_SMEM);

    // Prep
    pack_mask_kernel<<<S_DIM, N_DIM>>>(mask);
    split_w_kernel<<<QKV_COLS, 256>>>(Wqkv, wqt, QKV_COLS);
    split_w_kernel<<<D_MODEL, 256>>>(Wout, wot, D_MODEL);
    split_a_kernel<<<1024, 256>>>(x, abf);

    // 1) QKV projection (tensor cores; q-columns pre-scaled)
    {
        dim3 grid(QKV_COLS / 128, M_TOTAL / 128);
        gemm_mma_kernel<<<grid, 256, GEMM_SMEM>>>(abf, wqt, qkvbuf, nullptr,
                                                  QKV_COLS);
    }
    // 2) Attention (tensor cores; writes split bf16 output directly)
    {
        dim3 grid(HEADS, B_DIM, S_DIM);
        attn_mma_kernel<<<grid, 256, ATTN_SMEM_BYTES>>>(qkvbuf, abf);
    }
    // 3) Output projection (reads fused-split attn output)
    {
        dim3 grid(D_MODEL / 128, M_TOTAL / 128);
        gemm_mma_kernel<<<grid, 256, GEMM_SMEM>>>(abf, wot, out, bout,
                                                  D_MODEL);
    }
}

// round 14
// speedup vs baseline: 2.2146x; 1.0349x over previous
#include <cuda_runtime.h>
#include <cuda_bf16.h>
#include <cstdint>
#include <cstddef>

// Problem constants
#define S_DIM 64
#define B_DIM 4
#define N_DIM 256
#define D_MODEL 256
#define HEADS 8
#define DHEAD 32
#define INNER 256
#define QKV_COLS 768
#define M_TOTAL (S_DIM * B_DIM * N_DIM)   // 65536
#define SCALE 0.17677669529663687f
#define KS 512            // stored split width: [hi(256) | lo(256)]
#define NCHUNKS 12        // logical K' = 768 = 12 x 64

typedef unsigned long long ull;

// ---- mma / ldmatrix / cp.async helpers (baseline PTX, sm_80+) ----
__device__ __forceinline__ uint32_t smem_u32(const void* p) {
    uint32_t a;
    asm("{ .reg .u64 t; cvta.to.shared.u64 t, %1; cvt.u32.u64 %0, t; }"
        : "=r"(a) : "l"(p));
    return a;
}
__device__ __forceinline__ void ldm4(uint32_t* r, uint32_t addr) {
    asm volatile("ldmatrix.sync.aligned.m8n8.x4.shared.b16 {%0,%1,%2,%3}, [%4];"
        : "=r"(r[0]), "=r"(r[1]), "=r"(r[2]), "=r"(r[3]) : "r"(addr));
}
__device__ __forceinline__ void mma16816(float* c, const uint32_t* a,
                                         uint32_t b0, uint32_t b1) {
    asm volatile("mma.sync.aligned.m16n8k16.row.col.f32.bf16.bf16.f32 "
        "{%0,%1,%2,%3}, {%4,%5,%6,%7}, {%8,%9}, {%0,%1,%2,%3};"
        : "+f"(c[0]), "+f"(c[1]), "+f"(c[2]), "+f"(c[3])
        : "r"(a[0]), "r"(a[1]), "r"(a[2]), "r"(a[3]), "r"(b0), "r"(b1));
}
__device__ __forceinline__ void cp16(uint32_t s, const void* g) {
    asm volatile("cp.async.cg.shared.global [%0], [%1], 16;" :: "r"(s), "l"(g));
}
__device__ __forceinline__ void cp_commit() {
    asm volatile("cp.async.commit_group;" ::: "memory");
}
template <int N>
__device__ __forceinline__ void cp_wait() {
    asm volatile("cp.async.wait_group %0;" :: "n"(N) : "memory");
}
// pack two f32 into bf16x2: low half = lo arg, high half = hi arg
__device__ __forceinline__ uint32_t packbf(float lo, float hi) {
    uint32_t r;
    asm("cvt.rn.bf16x2.f32 %0, %1, %2;" : "=r"(r) : "f"(hi), "f"(lo));
    return r;
}
__device__ __forceinline__ float bf_lo(uint32_t u) { return __uint_as_float(u << 16); }
__device__ __forceinline__ float bf_hi(uint32_t u) { return __uint_as_float(u & 0xffff0000u); }

// Scratch (allocation-free rule: __device__ globals)
__device__ float g_qkv[(size_t)M_TOTAL * QKV_COLS];            // 192 MB
__device__ __nv_bfloat16 g_abf[(size_t)M_TOTAL * KS];          // 67 MB (split A)
__device__ __nv_bfloat16 g_wqt[(size_t)QKV_COLS * KS];         // W_qkv^T split
__device__ __nv_bfloat16 g_wot[(size_t)D_MODEL * KS];          // W_out^T split
__device__ unsigned g_maskpack[S_DIM][N_DIM][8];

// ---------------------------------------------------------------------------
// Prep kernels
// ---------------------------------------------------------------------------
__global__ void pack_mask_kernel(const int* __restrict__ mask) {
    const int s = blockIdx.x, i = threadIdx.x;
    const int* p = mask + ((size_t)s * N_DIM + i) * N_DIM;
    #pragma unroll
    for (int c = 0; c < 8; c++) {
        unsigned bits = 0;
        #pragma unroll 8
        for (int bb = 0; bb < 32; bb++)
            bits |= (unsigned)(p[c * 32 + bb] != 0) << bb;
        g_maskpack[s][i][c] = bits;
    }
}

// split fp32 [rows,256] -> bf16 [rows, hi256|lo256], grid-stride float4
__global__ __launch_bounds__(256)
void split_a_kernel(const float* __restrict__ src,
                    __nv_bfloat16* __restrict__ dst) {
    const int nf4 = M_TOTAL * 64;   // total float4s
    for (int idx = blockIdx.x * blockDim.x + threadIdx.x; idx < nf4;
         idx += gridDim.x * blockDim.x) {
        int row = idx >> 6;
        int c4 = (idx & 63) * 4;
        float4 v = *(const float4*)(src + (size_t)row * 256 + c4);
        uint32_t h0 = packbf(v.x, v.y);
        uint32_t h1 = packbf(v.z, v.w);
        uint32_t l0 = packbf(v.x - bf_lo(h0), v.y - bf_hi(h0));
        uint32_t l1 = packbf(v.z - bf_lo(h1), v.w - bf_hi(h1));
        __nv_bfloat16* d = dst + (size_t)row * KS;
        *(uint2*)(d + c4) = make_uint2(h0, h1);
        *(uint2*)(d + 256 + c4) = make_uint2(l0, l1);
    }
}

// W [256 (k), Ncols] fp32 -> Wt bf16 [Ncols (n)][hi256|lo256].
// For the QKV weight (Ncols==768), q columns (n<256) are pre-scaled by SCALE.
__global__ void split_w_kernel(const float* __restrict__ W,
                               __nv_bfloat16* __restrict__ Wt, int Ncols) {
    const int n = blockIdx.x;
    const int k = threadIdx.x;
    float w = W[(size_t)k * Ncols + n];
    if (Ncols == QKV_COLS && n < 256) w *= SCALE;
    __nv_bfloat16 hi = __float2bfloat16_rn(w);
    __nv_bfloat16 lo = __float2bfloat16_rn(w - __bfloat162float(hi));
    __nv_bfloat16* d = Wt + (size_t)n * KS;
    d[k] = hi; d[256 + k] = lo;
}

// ---------------------------------------------------------------------------
// Tensor-core GEMM: C = A' x B'^T, logical K' = 768, 3-stage cp.async pipe.
// ---------------------------------------------------------------------------
#define GEMM_SMEM (96 * 1024)   // 3 x (A 16K + B 16K)

__constant__ int c_cmapA[NCHUNKS] = {0,1,2,3,4,5,6,7,0,1,2,3};
__constant__ int c_cmapB[NCHUNKS] = {0,1,2,3,0,1,2,3,4,5,6,7};

__global__ __launch_bounds__(256, 2)
void gemm_mma_kernel(const __nv_bfloat16* __restrict__ A,
                     const __nv_bfloat16* __restrict__ Bt,
                     float* __restrict__ C, const float* __restrict__ bias,
                     int Ntot) {
    extern __shared__ __align__(1024) char smx[];
    const uint32_t sb = smem_u32(smx);
    const int tid = threadIdx.x;
    const int lane = tid & 31, w = tid >> 5;
    const int bx = blockIdx.x, by = blockIdx.y;
    const size_t arow0 = (size_t)by * 128;
    const size_t brow0 = (size_t)bx * 128;
    const int mrow = (w & 3) * 32;
    const int ncol = (w >> 2) * 64;

    uint32_t aoff[2], boff[4];
    const uint32_t khA = (lane >> 4) * 16;
    const uint32_t khB = ((lane >> 3) & 1) * 16;
    #pragma unroll
    for (int mt = 0; mt < 2; mt++) {
        uint32_t rp = (uint32_t)(mrow + mt * 16 + (lane & 15)) * 128;
        aoff[mt] = rp ^ ((rp >> 3) & 0x70);
    }
    #pragma unroll
    for (int nt = 0; nt < 4; nt++) {
        uint32_t n = ncol + nt * 16 + (lane & 7) + ((lane >> 4) << 3);
        uint32_t rp = n * 128;
        boff[nt] = rp ^ ((rp >> 3) & 0x70);
    }

    const char* Abase = (const char*)(A + arow0 * KS);
    const char* Bbase = (const char*)(Bt + brow0 * KS);
    const int crow = tid >> 1;
    const int cpart = (tid & 1) * 4;

    float acc[2][8][4];
    #pragma unroll
    for (int mt = 0; mt < 2; mt++)
        #pragma unroll
        for (int nt = 0; nt < 8; nt++)
            #pragma unroll
            for (int q = 0; q < 4; q++) acc[mt][nt][q] = 0.0f;

    auto issue = [&](int c, int buf) {
        const char* Ac = Abase + c_cmapA[c] * 128;
        const char* Bc = Bbase + c_cmapB[c] * 128;
        uint32_t sA = sb + buf * 16384;
        uint32_t sB = sb + 49152 + buf * 16384;
        #pragma unroll
        for (int p = 0; p < 4; p++) {
            uint32_t off = (uint32_t)crow * 128 + (cpart + p) * 16;
            uint32_t sw = off ^ ((off >> 3) & 0x70);
            cp16(sA + sw, Ac + (size_t)crow * (KS * 2) + (cpart + p) * 16);
            cp16(sB + sw, Bc + (size_t)crow * (KS * 2) + (cpart + p) * 16);
        }
        cp_commit();
    };

    issue(0, 0);
    issue(1, 1);
    for (int c = 0; c < NCHUNKS; c++) {
        const int buf = c % 3;
        if (c + 2 < NCHUNKS) {
            issue(c + 2, (c + 2) % 3);
            cp_wait<2>();
        } else if (c + 1 < NCHUNKS) {
            cp_wait<1>();
        } else {
            cp_wait<0>();
        }
        __syncthreads();

        const uint32_t sA = sb + buf * 16384;
        const uint32_t sB = sb + 49152 + buf * 16384;
        #pragma unroll
        for (int ks = 0; ks < 4; ks++) {
            uint32_t a[2][4], b[4][4];
            #pragma unroll
            for (int mt = 0; mt < 2; mt++)
                ldm4(a[mt], sA + (aoff[mt] ^ (ks * 32 + khA)));
            #pragma unroll
            for (int nt = 0; nt < 4; nt++)
                ldm4(b[nt], sB + (boff[nt] ^ (ks * 32 + khB)));
            #pragma unroll
            for (int mt = 0; mt < 2; mt++)
                #pragma unroll
                for (int nt = 0; nt < 4; nt++) {
                    mma16816(acc[mt][2 * nt + 0], a[mt], b[nt][0], b[nt][1]);
                    mma16816(acc[mt][2 * nt + 1], a[mt], b[nt][2], b[nt][3]);
                }
        }
        __syncthreads();
    }

    const int g = lane >> 2, t4 = lane & 3;
    #pragma unroll
    for (int mt = 0; mt < 2; mt++) {
        #pragma unroll
        for (int sub = 0; sub < 2; sub++) {
            size_t row = arow0 + mrow + mt * 16 + g + sub * 8;
            float* Cr = C + row * Ntot + brow0;
            #pragma unroll
            for (int nt = 0; nt < 8; nt++) {
                int col = ncol + nt * 8 + 2 * t4;
                float2 v = make_float2(acc[mt][nt][sub * 2 + 0],
                                       acc[mt][nt][sub * 2 + 1]);
                if (bias) {
                    v.x += __ldg(bias + brow0 + col);
                    v.y += __ldg(bias + brow0 + col + 1);
                }
                *(float2*)(Cr + col) = v;
            }
        }
    }
}

// ---------------------------------------------------------------------------
// MMA flash-attention: one CTA per (s,b,h), 512 threads = 16 warps x 16 rows.
// Same math as the verified 8-warp version; halved per-thread register
// footprint doubles warps/SMSP for latency hiding.
// ---------------------------------------------------------------------------
#define AQ_OFF 0
#define AK_OFF 32768
#define AV_OFF 65536
#define AM_OFF 98304
#define ATTN_SMEM_BYTES (98304 + 8192)

__global__ __launch_bounds__(512, 1)
void attn_mma_kernel(const float* __restrict__ qkv,
                     __nv_bfloat16* __restrict__ outsp) {
    extern __shared__ __align__(1024) char smx[];
    const uint32_t sb = smem_u32(smx);
    const int tid = threadIdx.x;
    const int lane = tid & 31, w = tid >> 5;   // w = 0..15
    const int g = lane >> 2, t4 = lane & 3;
    const int h = blockIdx.x, b = blockIdx.y, s = blockIdx.z;
    const size_t base = ((size_t)(s * B_DIM + b) * N_DIM) * QKV_COLS;

    // ---- load + split phase (2048 work items over 512 threads) ----
    unsigned* sM = (unsigned*)(smx + AM_OFF);
    #pragma unroll
    for (int t = 0; t < 4; t++) {
        int idx = t * 512 + tid;
        int j = idx >> 3, d4 = (idx & 7) * 4;
        const float* rowp = qkv + base + (size_t)j * QKV_COLS + h * DHEAD;
        float4 qv = *(const float4*)(rowp + d4);
        float4 kv = *(const float4*)(rowp + INNER + d4);
        float qs[4] = {qv.x, qv.y, qv.z, qv.w};
        float kk[4] = {kv.x, kv.y, kv.z, kv.w};
        uint32_t qh[2], ql[2], kh[2], kl[2];
        #pragma unroll
        for (int p = 0; p < 2; p++) {
            float a0 = qs[2 * p], a1 = qs[2 * p + 1];
            uint32_t uh = packbf(a0, a1);
            qh[p] = uh;
            ql[p] = packbf(a0 - bf_lo(uh), a1 - bf_hi(uh));
            float b0 = kk[2 * p], b1 = kk[2 * p + 1];
            uint32_t vh = packbf(b0, b1);
            kh[p] = vh;
            kl[p] = packbf(b0 - bf_lo(vh), b1 - bf_hi(vh));
        }
        uint32_t offh = (uint32_t)j * 128 + d4 * 2;
        uint32_t offl = offh + 64;
        uint32_t swh = offh ^ ((offh >> 3) & 0x70);
        uint32_t swl = offl ^ ((offl >> 3) & 0x70);
        *(uint2*)(smx + AQ_OFF + swh) = make_uint2(qh[0], qh[1]);
        *(uint2*)(smx + AQ_OFF + swl) = make_uint2(ql[0], ql[1]);
        *(uint2*)(smx + AK_OFF + swh) = make_uint2(kh[0], kh[1]);
        *(uint2*)(smx + AK_OFF + swl) = make_uint2(kl[0], kl[1]);
        float4 vv = *(const float4*)(rowp + 2 * INNER + d4);
        float ve[4] = {vv.x, vv.y, vv.z, vv.w};
        #pragma unroll
        for (int e = 0; e < 4; e++) {
            int d = d4 + e;
            __nv_bfloat16 hi = __float2bfloat16_rn(ve[e]);
            __nv_bfloat16 lo = __float2bfloat16_rn(ve[e] - __bfloat162float(hi));
            uint32_t oh = (uint32_t)d * 512 + j * 2;
            uint32_t ol = (uint32_t)(d + 32) * 512 + j * 2;
            *(__nv_bfloat16*)(smx + AV_OFF + (oh ^ (((oh >> 9) & 7) << 4))) = hi;
            *(__nv_bfloat16*)(smx + AV_OFF + (ol ^ (((ol >> 9) & 7) << 4))) = lo;
        }
        sM[idx] = g_maskpack[s][idx >> 3][idx & 7];
    }
    __syncthreads();

    const uint32_t khA = (lane >> 4) * 16;
    const uint32_t khB = ((lane >> 3) & 1) * 16;
    uint32_t qroff;
    {
        uint32_t rp = (uint32_t)(w * 16 + (lane & 15)) * 128;
        qroff = rp ^ ((rp >> 3) & 0x70);
    }
    uint32_t qf[4][4];
    #pragma unroll
    for (int kt = 0; kt < 4; kt++)
        ldm4(qf[kt], sb + AQ_OFF + (qroff ^ (kt * 32 + khA)));
    uint32_t vroffh[2], vroffl[2];
    #pragma unroll
    for (int dn = 0; dn < 2; dn++) {
        uint32_t nh = dn * 16 + (lane & 7) + ((lane >> 4) << 3);
        uint32_t rph = nh * 512;
        vroffh[dn] = rph ^ (((rph >> 9) & 7) << 4);
        uint32_t rpl = (nh + 32) * 512;
        vroffl[dn] = rpl ^ (((rpl >> 9) & 7) << 4);
    }

    float oacc[4][4];
    #pragma unroll
    for (int nt = 0; nt < 4; nt++)
        #pragma unroll
        for (int q = 0; q < 4; q++) oacc[nt][q] = 0.0f;
    float lsum[2] = {0.0f, 0.0f};

    const int KPA[6] = {0, 1, 2, 3, 0, 1};
    const int KPB[6] = {0, 1, 0, 1, 2, 3};

    for (int jt = 0; jt < 4; jt++) {
        const int j0 = jt * 64;
        float sfrag[8][4];
        #pragma unroll
        for (int nt = 0; nt < 8; nt++)
            #pragma unroll
            for (int q = 0; q < 4; q++) sfrag[nt][q] = 0.0f;

        // ---- S = Q K^T ----
        #pragma unroll
        for (int nt = 0; nt < 4; nt++) {
            uint32_t n = (uint32_t)(j0 + nt * 16 + (lane & 7) + ((lane >> 4) << 3));
            uint32_t rp = n * 128;
            uint32_t kro = rp ^ ((rp >> 3) & 0x70);
            uint32_t kb[4][4];
            #pragma unroll
            for (int kt = 0; kt < 4; kt++)
                ldm4(kb[kt], sb + AK_OFF + (kro ^ (kt * 32 + khB)));
            #pragma unroll
            for (int pp = 0; pp < 6; pp++) {
                mma16816(sfrag[2 * nt + 0], qf[KPA[pp]],
                         kb[KPB[pp]][0], kb[KPB[pp]][1]);
                mma16816(sfrag[2 * nt + 1], qf[KPA[pp]],
                         kb[KPB[pp]][2], kb[KPB[pp]][3]);
            }
        }

        // ---- mask + exp + rowsum ----
        {
            int i0 = w * 16 + g;
            unsigned mwA0 = sM[i0 * 8 + 2 * jt], mwA1 = sM[i0 * 8 + 2 * jt + 1];
            unsigned mwB0 = sM[(i0 + 8) * 8 + 2 * jt], mwB1 = sM[(i0 + 8) * 8 + 2 * jt + 1];
            #pragma unroll
            for (int nt = 0; nt < 8; nt++) {
                unsigned mA = (nt < 4) ? mwA0 : mwA1;
                unsigned mB = (nt < 4) ? mwB0 : mwB1;
                int bb = (nt & 3) * 8 + 2 * t4;
                float* c = sfrag[nt];
                float p0 = ((mA >> bb) & 1u) ? __expf(c[0]) : 0.0f;
                float p1 = ((mA >> (bb + 1)) & 1u) ? __expf(c[1]) : 0.0f;
                float p2 = ((mB >> bb) & 1u) ? __expf(c[2]) : 0.0f;
                float p3 = ((mB >> (bb + 1)) & 1u) ? __expf(c[3]) : 0.0f;
                c[0] = p0; c[1] = p1; c[2] = p2; c[3] = p3;
                lsum[0] += p0 + p1;
                lsum[1] += p2 + p3;
            }
        }

        // ---- P V: 3 terms ----
        #pragma unroll
        for (int jkt = 0; jkt < 4; jkt++) {
            uint32_t koff = (uint32_t)(j0 * 2 + jkt * 32) + khB;
            uint32_t vbh[2][4], vbl[2][4];
            #pragma unroll
            for (int dn = 0; dn < 2; dn++) {
                ldm4(vbh[dn], sb + AV_OFF + (vroffh[dn] ^ koff));
                ldm4(vbl[dn], sb + AV_OFF + (vroffl[dn] ^ koff));
            }
            float* cA = sfrag[2 * jkt + 0];
            float* cB = sfrag[2 * jkt + 1];
            uint32_t ahi[4], alo[4];
            ahi[0] = packbf(cA[0], cA[1]);
            ahi[1] = packbf(cA[2], cA[3]);
            ahi[2] = packbf(cB[0], cB[1]);
            ahi[3] = packbf(cB[2], cB[3]);
            alo[0] = packbf(cA[0] - bf_lo(ahi[0]), cA[1] - bf_hi(ahi[0]));
            alo[1] = packbf(cA[2] - bf_lo(ahi[1]), cA[3] - bf_hi(ahi[1]));
            alo[2] = packbf(cB[0] - bf_lo(ahi[2]), cB[1] - bf_hi(ahi[2]));
            alo[3] = packbf(cB[2] - bf_lo(ahi[3]), cB[3] - bf_hi(ahi[3]));
            #pragma unroll
            for (int dn = 0; dn < 2; dn++) {
                mma16816(oacc[2 * dn + 0], ahi, vbh[dn][0], vbh[dn][1]);
                mma16816(oacc[2 * dn + 1], ahi, vbh[dn][2], vbh[dn][3]);
                mma16816(oacc[2 * dn + 0], alo, vbh[dn][0], vbh[dn][1]);
                mma16816(oacc[2 * dn + 1], alo, vbh[dn][2], vbh[dn][3]);
                mma16816(oacc[2 * dn + 0], ahi, vbl[dn][0], vbl[dn][1]);
                mma16816(oacc[2 * dn + 1], ahi, vbl[dn][2], vbl[dn][3]);
            }
        }
    }

    // ---- normalize + split + store ----
    const size_t rbase = (size_t)(s * B_DIM + b) * N_DIM;
    #pragma unroll
    for (int h2 = 0; h2 < 2; h2++) {
        float l = lsum[h2];
        l += __shfl_xor_sync(0xffffffffu, l, 1);
        l += __shfl_xor_sync(0xffffffffu, l, 2);
        float inv = 1.0f / l;
        int i = w * 16 + g + 8 * h2;
        __nv_bfloat16* o = outsp + (rbase + i) * KS + h * DHEAD;
        #pragma unroll
        for (int nt = 0; nt < 4; nt++) {
            int d = nt * 8 + 2 * t4;
            float v0 = oacc[nt][2 * h2 + 0] * inv;
            float v1 = oacc[nt][2 * h2 + 1] * inv;
            uint32_t uh = packbf(v0, v1);
            uint32_t ul = packbf(v0 - bf_lo(uh), v1 - bf_hi(uh));
            *(uint32_t*)(o + d) = uh;
            *(uint32_t*)(o + 256 + d) = ul;
        }
    }
}

// ---------------------------------------------------------------------------
// Launch
// ---------------------------------------------------------------------------
extern "C" void kernel_launch(void* const* d_in, const int* in_sizes, int n_in,
                              void* d_out, int out_size) {
    const float* x    = (const float*)d_in[0];
    const int*   mask = (const int*)d_in[1];
    const float* Wqkv = (const float*)d_in[2];
    const float* Wout = (const float*)d_in[3];
    const float* bout = (const float*)d_in[4];
    float* out = (float*)d_out;

    float* qkvbuf = nullptr;
    __nv_bfloat16 *abf = nullptr, *wqt = nullptr, *wot = nullptr;
    cudaGetSymbolAddress((void**)&qkvbuf, g_qkv);
    cudaGetSymbolAddress((void**)&abf, g_abf);
    cudaGetSymbolAddress((void**)&wqt, g_wqt);
    cudaGetSymbolAddress((void**)&wot, g_wot);

    cudaFuncSetAttribute(attn_mma_kernel, cudaFuncAttributeMaxDynamicSharedMemorySize,
                         ATTN_SMEM_BYTES);
    cudaFuncSetAttribute(gemm_mma_kernel, cudaFuncAttributeMaxDynamicSharedMemorySize,
                         GEMM_SMEM);

    // Prep
    pack_mask_kernel<<<S_DIM, N_DIM>>>(mask);
    split_w_kernel<<<QKV_COLS, 256>>>(Wqkv, wqt, QKV_COLS);
    split_w_kernel<<<D_MODEL, 256>>>(Wout, wot, D_MODEL);
    split_a_kernel<<<1024, 256>>>(x, abf);

    // 1) QKV projection (tensor cores; q-columns pre-scaled)
    {
        dim3 grid(QKV_COLS / 128, M_TOTAL / 128);
        gemm_mma_kernel<<<grid, 256, GEMM_SMEM>>>(abf, wqt, qkvbuf, nullptr,
                                                  QKV_COLS);
    }
    // 2) Attention (tensor cores; 512 threads; writes split bf16 output)
    {
        dim3 grid(HEADS, B_DIM, S_DIM);
        attn_mma_kernel<<<grid, 512, ATTN_SMEM_BYTES>>>(qkvbuf, abf);
    }
    // 3) Output projection (reads fused-split attn output)
    {
        dim3 grid(D_MODEL / 128, M_TOTAL / 128);
        gemm_mma_kernel<<<grid, 256, GEMM_SMEM>>>(abf, wot, out, bout,
                                                  D_MODEL);
    }
}